// round 14
// baseline (speedup 1.0000x reference)
#include <cuda_runtime.h>
#include <math.h>

#define BB 8
#define CC 64
#define NN 256
#define M1 20
#define M2 20
#define RR 40
#define MODES 800
#define LL 3
#define FCN 128
#define BP 264          // B-matrix smem row pitch (floats)
#define AP 68           // A-matrix smem row pitch (fc12)
#define CAP 92          // concatenated A pitch (ilayer)

// ---------------- device scratch ----------------
__device__ float g_h[BB * CC * NN * NN];
__device__ float g_t1p[BB * CC * NN * M2];         // y-first DCT temp [row=(bc,x)][s]
__device__ float g_spec[MODES * BB * CC];
__device__ float g_spec2[BB * CC * MODES];
__device__ float g_t2[BB * CC * NN * M2];
__device__ float g_Wm[LL * MODES * CC * CC];
__device__ float g_F1[RR * NN];
__device__ float g_F2[M2 * NN];
__device__ float g_G1[NN * RR];
__device__ float g_G2[NN * M2];

// ---------------- helpers ----------------
__device__ __forceinline__ unsigned f2tf(float f) {
    unsigned u; asm("cvt.rna.tf32.f32 %0,%1;" : "=r"(u) : "f"(f)); return u;
}
__device__ __forceinline__ void split_tf(float v, unsigned& hi, unsigned& lo) {
    unsigned h = f2tf(v);
    hi = h;
    lo = f2tf(v - __uint_as_float(h));
}
__device__ __forceinline__ void mma8(float& d0, float& d1, float& d2, float& d3,
                                     unsigned a0, unsigned a1, unsigned a2, unsigned a3,
                                     unsigned b0, unsigned b1) {
    asm("mma.sync.aligned.m16n8k8.row.col.f32.tf32.tf32.f32 "
        "{%0,%1,%2,%3},{%4,%5,%6,%7},{%8,%9},{%0,%1,%2,%3};"
        : "+f"(d0), "+f"(d1), "+f"(d2), "+f"(d3)
        : "r"(a0), "r"(a1), "r"(a2), "r"(a3), "r"(b0), "r"(b1));
}
#define MMA3(ACC, AH0,AH1,AH2,AH3, AL0,AL1,AL2,AL3, BH0,BH1, BL0,BL1)             \
    do {                                                                           \
        mma8(ACC[0],ACC[1],ACC[2],ACC[3], AH0,AH1,AH2,AH3, BL0,BL1);               \
        mma8(ACC[0],ACC[1],ACC[2],ACC[3], AL0,AL1,AL2,AL3, BH0,BH1);               \
        mma8(ACC[0],ACC[1],ACC[2],ACC[3], AH0,AH1,AH2,AH3, BH0,BH1);               \
    } while (0)
#define MMA3S(ACC, ACG, AH0,AH1,AH2,AH3, AL0,AL1,AL2,AL3, BH0,BH1, BL0,BL1)       \
    do {                                                                           \
        mma8(ACG[0],ACG[1],ACG[2],ACG[3], AH0,AH1,AH2,AH3, BL0,BL1);               \
        mma8(ACG[0],ACG[1],ACG[2],ACG[3], AL0,AL1,AL2,AL3, BH0,BH1);               \
        mma8(ACC[0],ACC[1],ACC[2],ACC[3], AH0,AH1,AH2,AH3, BH0,BH1);               \
    } while (0)

__device__ __forceinline__ float ftanh(float x) {
    float e = __expf(2.f * x);
    return 1.f - __fdividef(2.f, e + 1.f);
}

// ---------------- DCT basis tables ----------------
__global__ void k_init() {
    int x = blockIdx.x, t = threadIdx.x;
    if (t < RR) {
        int k = (t < M1) ? t : (216 + t);
        int m = (k * x) % 510;
        float cv = (float)cospi((double)m / 255.0);
        float cx = (x == 0 || x == 255) ? 1.f : 2.f;
        g_F1[t * NN + x] = cx * cv;
        float ck = (k == 0 || k == 255) ? 1.f : 2.f;
        g_G1[x * RR + t] = ck * cv;
    }
    if (t < M2) {
        int m = (t * x) % 510;
        float cv = (float)cospi((double)m / 255.0);
        float cy = (x == 0 || x == 255) ? 1.f : 2.f;
        g_F2[t * NN + x] = cy * cv;
        float cs = (t == 0) ? 1.f : 2.f;
        g_G2[x * M2 + t] = cs * cv;
    }
}

// ---------------- spectral weight transpose ----------------
__global__ void k_wtrans(const float* __restrict__ w1, const float* __restrict__ w2) {
    __shared__ float tile[32][33];
    int l = blockIdx.z >> 1, half = blockIdx.z & 1;
    const float* src = (half ? w2 : w1) + (size_t)l * CC * CC * (M1 * M2);
    float* dst = g_Wm + ((size_t)l * MODES + half * 400) * (CC * CC);
    int col = blockIdx.x * 32 + threadIdx.x;
    int row = blockIdx.y * 32 + threadIdx.y;
    if (col < 400) tile[threadIdx.y][threadIdx.x] = src[(size_t)row * 400 + col];
    __syncthreads();
    int drow = blockIdx.x * 32 + threadIdx.y;
    int dcol = blockIdx.y * 32 + threadIdx.x;
    if (drow < 400) dst[(size_t)drow * 4096 + dcol] = tile[threadIdx.x][threadIdx.y];
}

// ---------------- fc0 ----------------
__global__ void k_fc0(const float* __restrict__ x, const float* __restrict__ w,
                      const float* __restrict__ bias) {
    __shared__ float sw[3][CC];
    __shared__ float sb[CC];
    int xi = blockIdx.x, b = blockIdx.y, y = threadIdx.x;
    if (y < CC) { sw[0][y] = w[y]; sw[1][y] = w[CC + y]; sw[2][y] = w[2 * CC + y]; sb[y] = bias[y]; }
    __syncthreads();
    const float* xp = x + (((size_t)b * NN + xi) * NN + y) * 3;
    float d0 = xp[0], d1 = xp[1], d2 = xp[2];
    float* hp = g_h + ((size_t)(b * CC) * NN + xi) * NN + y;
#pragma unroll
    for (int c = 0; c < CC; c++)
        hp[(size_t)c * (NN * NN)] = sb[c] + d0 * sw[0][c] + d1 * sw[1][c] + d2 * sw[2][c];
}

// ---------------- forward DCT stage 1' (y-first, streaming 3xTF32, split accumulators) ----
__global__ __launch_bounds__(256) void k_s1p() {
    extern __shared__ unsigned smu[];
    unsigned* sBh = smu;               // [256][24]
    unsigned* sBl = smu + 256 * 24;
    int tid = threadIdx.x;
    int wid = tid >> 5, lane = tid & 31, gid = lane >> 2, tig = lane & 3;

    for (int idx = tid; idx < 256 * 24; idx += 256) {
        int y = idx / 24, s = idx % 24;
        float v = (s < 20) ? g_F2[s * NN + y] : 0.f;
        split_tf(v, sBh[idx], sBl[idx]);
    }
    __syncthreads();

    size_t row0 = (size_t)blockIdx.x * 128 + wid * 16;
    const float* A0 = g_h + (row0 + gid) * NN;
    const float* A1 = g_h + (row0 + gid + 8) * NN;

    float acc[3][4], acg[3][4];
#pragma unroll
    for (int i = 0; i < 3; i++) {
        acc[i][0] = acc[i][1] = acc[i][2] = acc[i][3] = 0.f;
        acg[i][0] = acg[i][1] = acg[i][2] = acg[i][3] = 0.f;
    }

#pragma unroll 4
    for (int k0 = 0; k0 < 256; k0 += 8) {
        float av0 = __ldg(&A0[k0 + tig]);
        float av1 = __ldg(&A1[k0 + tig]);
        float av2 = __ldg(&A0[k0 + tig + 4]);
        float av3 = __ldg(&A1[k0 + tig + 4]);
        unsigned ah0, al0, ah1, al1, ah2, al2, ah3, al3;
        split_tf(av0, ah0, al0); split_tf(av1, ah1, al1);
        split_tf(av2, ah2, al2); split_tf(av3, ah3, al3);
#pragma unroll
        for (int nt = 0; nt < 3; nt++) {
            int n = nt * 8 + gid;
            unsigned bh0 = sBh[(k0 + tig) * 24 + n];
            unsigned bh1 = sBh[(k0 + tig + 4) * 24 + n];
            unsigned bl0 = sBl[(k0 + tig) * 24 + n];
            unsigned bl1 = sBl[(k0 + tig + 4) * 24 + n];
            MMA3S(acc[nt], acg[nt], ah0,ah1,ah2,ah3, al0,al1,al2,al3, bh0,bh1, bl0,bl1);
        }
    }

    float* t0 = g_t1p + (row0 + gid) * M2;
    float* t1 = g_t1p + (row0 + gid + 8) * M2;
#pragma unroll
    for (int nt = 0; nt < 3; nt++) {
        int c0 = nt * 8 + tig * 2;
        if (c0 < 20) {
            *(float2*)&t0[c0] = make_float2(acc[nt][0] + acg[nt][0], acc[nt][1] + acg[nt][1]);
            *(float2*)&t1[c0] = make_float2(acc[nt][2] + acg[nt][2], acc[nt][3] + acg[nt][3]);
        }
    }
}

// ---------------- forward DCT stage 2' (x contraction, exact fp32) ----------------
__global__ __launch_bounds__(256) void k_s2p() {
    __shared__ float sS[NN * M2];      // [x][s]
    int bc = blockIdx.x, t = threadIdx.x;
    const float4* tp = (const float4*)(g_t1p + (size_t)bc * NN * M2);
    for (int i = t; i < NN * 5; i += 256) ((float4*)sS)[i] = tp[i];
    __syncthreads();
    if (t < 200) {
        int a = t / 5, q = t % 5;
        float4 acc = make_float4(0.f, 0.f, 0.f, 0.f);
        const float* f1 = g_F1 + a * NN;
#pragma unroll 4
        for (int x = 0; x < NN; x++) {
            float f = __ldg(&f1[x]);
            float4 v = *(const float4*)&sS[x * M2 + 4 * q];
            acc.x += f * v.x; acc.y += f * v.y; acc.z += f * v.z; acc.w += f * v.w;
        }
        int m0 = a * M2 + 4 * q;
        g_spec[(size_t)(m0 + 0) * (BB * CC) + bc] = acc.x;
        g_spec[(size_t)(m0 + 1) * (BB * CC) + bc] = acc.y;
        g_spec[(size_t)(m0 + 2) * (BB * CC) + bc] = acc.z;
        g_spec[(size_t)(m0 + 3) * (BB * CC) + bc] = acc.w;
    }
}

// ---------------- per-mode channel mix (exact fp32) ----------------
__global__ __launch_bounds__(256) void k_mix(int l) {
    __shared__ float sW[CC * CC];
    __shared__ float sS[BB * CC];
    int m = blockIdx.x, t = threadIdx.x;
    const float* Wp = g_Wm + ((size_t)l * MODES + m) * (CC * CC);
    for (int i = t; i < CC * CC; i += 256) sW[i] = Wp[i];
    for (int i = t; i < BB * CC; i += 256) sS[i] = g_spec[(size_t)m * (BB * CC) + i];
    __syncthreads();
#pragma unroll
    for (int k = 0; k < 2; k++) {
        int idx = t + k * 256;
        int b = idx >> 6, o = idx & 63;
        float acc = 0.f;
#pragma unroll
        for (int i = 0; i < CC; i++) acc += sS[b * CC + i] * sW[i * CC + o];
        g_spec2[(size_t)(b * CC + o) * MODES + m] = acc;
    }
}

// ---------------- inverse stage 1 (exact fp32) ----------------
__global__ __launch_bounds__(256) void k_istage1() {
    __shared__ float sS[MODES];
    int bo = blockIdx.x, x = threadIdx.x;
    for (int i = x; i < MODES; i += 256) sS[i] = g_spec2[(size_t)bo * MODES + i];
    __syncthreads();
    float g1r[RR];
    const float4* gp = (const float4*)(g_G1 + x * RR);
#pragma unroll
    for (int j = 0; j < RR / 4; j++) {
        float4 v = gp[j];
        g1r[4 * j] = v.x; g1r[4 * j + 1] = v.y; g1r[4 * j + 2] = v.z; g1r[4 * j + 3] = v.w;
    }
    float acc[M2];
#pragma unroll
    for (int s = 0; s < M2; s++) acc[s] = 0.f;
#pragma unroll 4
    for (int r = 0; r < RR; r++) {
        float g = g1r[r];
#pragma unroll
        for (int s = 0; s < M2; s++) acc[s] += g * sS[r * M2 + s];
    }
    float* tp = g_t2 + ((size_t)bo * NN + x) * M2;
#pragma unroll
    for (int s = 0; s < M2; s++) tp[s] = acc[s];
}

// ---------------- fused layer update: unified K=88 concat GEMM, all pre-split ------------
// OUT(64x256) = [T2 | CW](64x88) * [G2T ; H](88x256) + bias, [tanh], in place
// A cols 0..23 = T2 (s), cols 24..87 = CW (i). B chunk 0 = G2T (24 rows), chunks 1..4 = H.
__global__ __launch_bounds__(512, 2) void k_ilayer_mma(const float* __restrict__ conv_w,
                                                       const float* __restrict__ conv_b,
                                                       int l, int do_tanh) {
    extern __shared__ unsigned smu[];
    unsigned* sAh = smu;                 // [64][CAP]
    unsigned* sAl = sAh + 64 * CAP;      // [64][CAP]
    unsigned* sBh = sAl + 64 * CAP;      // [24][BP] chunk buffer
    unsigned* sBl = sBh + 24 * BP;       // [24][BP]
    int x = blockIdx.x, b = blockIdx.y, tid = threadIdx.x;
    int wid = tid >> 5, lane = tid & 31, gid = lane >> 2, tig = lane & 3;
    int mt = wid & 3, nh = wid >> 2;
    int obase = mt * 16, ybase = nh * 64;

    // stage A_cat pre-split: [T2 | CW]
    const float* cw = conv_w + (size_t)l * CC * CC;
    const float* t2b = g_t2 + ((size_t)(b * 64) * NN + x) * M2;   // + o*NN*M2 per row
    for (int idx = tid; idx < 64 * CAP; idx += 512) {
        int o = idx / CAP, col = idx % CAP;
        float v;
        if (col < 24)       v = (col < 20) ? t2b[(size_t)o * (NN * M2) + col] : 0.f;
        else if (col < 88)  v = cw[o * 64 + (col - 24)];
        else                v = 0.f;
        split_tf(v, sAh[idx], sAl[idx]);
    }

    float bias0 = __ldg(&conv_b[l * 64 + obase + gid]);
    float bias1 = __ldg(&conv_b[l * 64 + obase + gid + 8]);
    float acc[8][4];
#pragma unroll
    for (int nt = 0; nt < 8; nt++) { acc[nt][0] = acc[nt][1] = bias0; acc[nt][2] = acc[nt][3] = bias1; }

    // chunk 0: G2T rows (24), A cols 0..23
    __syncthreads();
    for (int idx = tid; idx < 24 * NN; idx += 512) {
        int s = idx >> 8, y = idx & 255;
        float v = (s < 20) ? g_G2[y * M2 + s] : 0.f;
        split_tf(v, sBh[s * BP + y], sBl[s * BP + y]);
    }
    __syncthreads();
#pragma unroll
    for (int ks = 0; ks < 3; ks++) {
        int k0 = ks * 8;
        unsigned ah0 = sAh[(obase + gid) * CAP + k0 + tig];
        unsigned ah1 = sAh[(obase + gid + 8) * CAP + k0 + tig];
        unsigned ah2 = sAh[(obase + gid) * CAP + k0 + tig + 4];
        unsigned ah3 = sAh[(obase + gid + 8) * CAP + k0 + tig + 4];
        unsigned al0 = sAl[(obase + gid) * CAP + k0 + tig];
        unsigned al1 = sAl[(obase + gid + 8) * CAP + k0 + tig];
        unsigned al2 = sAl[(obase + gid) * CAP + k0 + tig + 4];
        unsigned al3 = sAl[(obase + gid + 8) * CAP + k0 + tig + 4];
#pragma unroll
        for (int nt = 0; nt < 8; nt++) {
            int n = ybase + nt * 8 + gid;
            unsigned bh0 = sBh[(k0 + tig) * BP + n];
            unsigned bh1 = sBh[(k0 + tig + 4) * BP + n];
            unsigned bl0 = sBl[(k0 + tig) * BP + n];
            unsigned bl1 = sBl[(k0 + tig + 4) * BP + n];
            MMA3(acc[nt], ah0,ah1,ah2,ah3, al0,al1,al2,al3, bh0,bh1, bl0,bl1);
        }
    }

    // chunks 1..4: H rows (16 each), A cols 24 + (hc-1)*16 ..
    for (int hc = 0; hc < 4; hc++) {
        __syncthreads();
        for (int idx = tid; idx < 16 * 64; idx += 512) {
            int i = idx >> 6, q = idx & 63;
            float4 v = *(const float4*)&g_h[(((size_t)(b * 64 + hc * 16 + i)) * NN + x) * NN + q * 4];
            unsigned h0, l0, h1, l1, h2, l2, h3, l3;
            split_tf(v.x, h0, l0); split_tf(v.y, h1, l1);
            split_tf(v.z, h2, l2); split_tf(v.w, h3, l3);
            *(uint4*)&sBh[i * BP + q * 4] = make_uint4(h0, h1, h2, h3);
            *(uint4*)&sBl[i * BP + q * 4] = make_uint4(l0, l1, l2, l3);
        }
        __syncthreads();
#pragma unroll
        for (int ks = 0; ks < 2; ks++) {
            int k0 = ks * 8;
            int ca = 24 + hc * 16 + k0 + tig;
            unsigned ah0 = sAh[(obase + gid) * CAP + ca];
            unsigned ah1 = sAh[(obase + gid + 8) * CAP + ca];
            unsigned ah2 = sAh[(obase + gid) * CAP + ca + 4];
            unsigned ah3 = sAh[(obase + gid + 8) * CAP + ca + 4];
            unsigned al0 = sAl[(obase + gid) * CAP + ca];
            unsigned al1 = sAl[(obase + gid + 8) * CAP + ca];
            unsigned al2 = sAl[(obase + gid) * CAP + ca + 4];
            unsigned al3 = sAl[(obase + gid + 8) * CAP + ca + 4];
#pragma unroll
            for (int nt = 0; nt < 8; nt++) {
                int n = ybase + nt * 8 + gid;
                unsigned bh0 = sBh[(k0 + tig) * BP + n];
                unsigned bh1 = sBh[(k0 + tig + 4) * BP + n];
                unsigned bl0 = sBl[(k0 + tig) * BP + n];
                unsigned bl1 = sBl[(k0 + tig + 4) * BP + n];
                MMA3(acc[nt], ah0,ah1,ah2,ah3, al0,al1,al2,al3, bh0,bh1, bl0,bl1);
            }
        }
    }

    int r0 = obase + gid, r1 = r0 + 8;
    float* h0 = &g_h[(((size_t)(b * 64 + r0)) * NN + x) * NN];
    float* h1 = &g_h[(((size_t)(b * 64 + r1)) * NN + x) * NN];
#pragma unroll
    for (int nt = 0; nt < 8; nt++) {
        int y0 = ybase + nt * 8 + tig * 2;
        float d0 = acc[nt][0], d1 = acc[nt][1], d2 = acc[nt][2], d3 = acc[nt][3];
        if (do_tanh) { d0 = ftanh(d0); d1 = ftanh(d1); d2 = ftanh(d2); d3 = ftanh(d3); }
        *(float2*)&h0[y0] = make_float2(d0, d1);
        *(float2*)&h1[y0] = make_float2(d2, d3);
    }
}

// ---------------- fc1 (tanh) + fc2 fused (3xTF32, B pre-split in staging) ----------------
__global__ __launch_bounds__(512, 2) void k_fc12_mma(const float* __restrict__ w1,
                                                     const float* __restrict__ b1,
                                                     const float* __restrict__ w2,
                                                     const float* __restrict__ b2,
                                                     float* __restrict__ out) {
    extern __shared__ unsigned smu[];
    float* sA = (float*)smu;                      // [128][AP] fp32
    unsigned* sHh = (unsigned*)(sA + 128 * AP);   // [32][BP]
    unsigned* sHl = sHh + 32 * BP;                // [32][BP]
    float* sred = (float*)(sHl + 32 * BP);        // [256]
    float* sb1  = sred + 256;                     // [128]
    float* sw2  = sb1 + 128;                      // [128]
    int x = blockIdx.x, b = blockIdx.y, tid = threadIdx.x;
    int wid = tid >> 5, lane = tid & 31, gid = lane >> 2, tig = lane & 3;
    int mt = wid & 7, nh = wid >> 3;
    int fbase = mt * 16, ybase = nh * 128;

    for (int idx = tid; idx < 128 * AP; idx += 512) {
        int f = idx / AP, c = idx % AP;
        sA[idx] = (c < 64) ? w1[c * FCN + f] : 0.f;
    }
    if (tid < 256) sred[tid] = 0.f;
    if (tid < 128) { sb1[tid] = b1[tid]; sw2[tid] = w2[tid]; }
    __syncthreads();

    float bias0 = sb1[fbase + gid], bias1 = sb1[fbase + gid + 8];
    float w20 = sw2[fbase + gid], w21 = sw2[fbase + gid + 8];
    float acc[16][4];
#pragma unroll
    for (int nt = 0; nt < 16; nt++) { acc[nt][0] = acc[nt][1] = bias0; acc[nt][2] = acc[nt][3] = bias1; }

    for (int hc = 0; hc < 2; hc++) {
        __syncthreads();
        for (int idx = tid; idx < 32 * 64; idx += 512) {
            int i = idx >> 6, q = idx & 63;
            float4 v = *(const float4*)&g_h[(((size_t)(b * 64 + hc * 32 + i)) * NN + x) * NN + q * 4];
            unsigned h0, l0, h1, l1, h2, l2, h3, l3;
            split_tf(v.x, h0, l0); split_tf(v.y, h1, l1);
            split_tf(v.z, h2, l2); split_tf(v.w, h3, l3);
            *(uint4*)&sHh[i * BP + q * 4] = make_uint4(h0, h1, h2, h3);
            *(uint4*)&sHl[i * BP + q * 4] = make_uint4(l0, l1, l2, l3);
        }
        __syncthreads();
#pragma unroll
        for (int ks = 0; ks < 4; ks++) {
            int k0 = ks * 8;
            int ca = hc * 32 + k0 + tig;
            unsigned ah0, al0, ah1, al1, ah2, al2, ah3, al3;
            split_tf(sA[(fbase + gid) * AP + ca], ah0, al0);
            split_tf(sA[(fbase + gid + 8) * AP + ca], ah1, al1);
            split_tf(sA[(fbase + gid) * AP + ca + 4], ah2, al2);
            split_tf(sA[(fbase + gid + 8) * AP + ca + 4], ah3, al3);
#pragma unroll
            for (int nt = 0; nt < 16; nt++) {
                int n = ybase + nt * 8 + gid;
                unsigned bh0 = sHh[(k0 + tig) * BP + n];
                unsigned bh1 = sHh[(k0 + tig + 4) * BP + n];
                unsigned bl0 = sHl[(k0 + tig) * BP + n];
                unsigned bl1 = sHl[(k0 + tig + 4) * BP + n];
                MMA3(acc[nt], ah0,ah1,ah2,ah3, al0,al1,al2,al3, bh0,bh1, bl0,bl1);
            }
        }
    }

#pragma unroll
    for (int nt = 0; nt < 16; nt++) {
        float p0 = ftanh(acc[nt][0]) * w20 + ftanh(acc[nt][2]) * w21;
        float p1 = ftanh(acc[nt][1]) * w20 + ftanh(acc[nt][3]) * w21;
#pragma unroll
        for (int m = 4; m < 32; m <<= 1) {
            p0 += __shfl_xor_sync(0xffffffffu, p0, m);
            p1 += __shfl_xor_sync(0xffffffffu, p1, m);
        }
        if (lane < 4) {
            int y0 = ybase + nt * 8 + lane * 2;
            atomicAdd(&sred[y0], p0);
            atomicAdd(&sred[y0 + 1], p1);
        }
    }
    __syncthreads();
    if (tid < 256)
        out[((size_t)b * NN + x) * NN + tid] = sred[tid] + __ldg(&b2[0]);
}

// ---------------- launch ----------------
extern "C" void kernel_launch(void* const* d_in, const int* in_sizes, int n_in,
                              void* d_out, int out_size) {
    const float* x      = (const float*)d_in[0];
    const float* fc0_w  = (const float*)d_in[1];
    const float* fc0_b  = (const float*)d_in[2];
    const float* sp_w1  = (const float*)d_in[3];
    const float* sp_w2  = (const float*)d_in[4];
    const float* conv_w = (const float*)d_in[5];
    const float* conv_b = (const float*)d_in[6];
    const float* fc1_w  = (const float*)d_in[7];
    const float* fc1_b  = (const float*)d_in[8];
    const float* fc2_w  = (const float*)d_in[9];
    const float* fc2_b  = (const float*)d_in[10];
    float* out = (float*)d_out;

    const int SM_S1P    = 2 * 256 * 24 * 4;                                      // 49152
    const int SM_ILAYER = (2 * 64 * CAP + 2 * 24 * BP) * 4;                      // 97792
    const int SM_FC12   = (128 * AP + 2 * 32 * BP + 256 + 128 + 128) * 4;        // 104448

    cudaFuncSetAttribute(k_s1p, cudaFuncAttributeMaxDynamicSharedMemorySize, SM_S1P);
    cudaFuncSetAttribute(k_ilayer_mma, cudaFuncAttributeMaxDynamicSharedMemorySize, SM_ILAYER);
    cudaFuncSetAttribute(k_fc12_mma, cudaFuncAttributeMaxDynamicSharedMemorySize, SM_FC12);

    k_init<<<NN, 256>>>();
    k_wtrans<<<dim3(13, 128, LL * 2), dim3(32, 32)>>>(sp_w1, sp_w2);
    k_fc0<<<dim3(NN, BB), 256>>>(x, fc0_w, fc0_b);

    for (int l = 0; l < LL; l++) {
        k_s1p<<<(BB * CC * NN) / 128, 256, SM_S1P>>>();
        k_s2p<<<BB * CC, 256>>>();
        k_mix<<<MODES, 256>>>(l);
        k_istage1<<<BB * CC, 256>>>();
        k_ilayer_mma<<<dim3(NN, BB), 512, SM_ILAYER>>>(conv_w, conv_b, l, (l != LL - 1) ? 1 : 0);
    }

    k_fc12_mma<<<dim3(NN, BB), 512, SM_FC12>>>(fc1_w, fc1_b, fc2_w, fc2_b, out);
}

// round 15
// speedup vs baseline: 1.0203x; 1.0203x over previous
#include <cuda_runtime.h>
#include <math.h>

#define BB 8
#define CC 64
#define NN 256
#define M1 20
#define M2 20
#define RR 40
#define MODES 800
#define LL 3
#define FCN 128
#define AP 68           // A-matrix smem row pitch (floats)
#define SBP 528         // s1p B pitch (words), 528 % 32 == 16 -> conflict-free uint4
#define IBP 520         // ilayer/fc12 B pitch (words), 520 % 32 == 8 -> conflict-free uint2

// ---------------- device scratch ----------------
__device__ float g_h[BB * CC * NN * NN];
__device__ float g_t1p[BB * CC * NN * M2];         // y-first DCT temp [row=(bc,x)][s]
__device__ float g_spec[MODES * BB * CC];
__device__ float g_spec2[BB * CC * MODES];
__device__ float g_t2[BB * CC * NN * M2];
__device__ float g_Wm[LL * MODES * CC * CC];
__device__ float g_F1[RR * NN];
__device__ float g_F2[M2 * NN];
__device__ float g_G1[NN * RR];
__device__ float g_G2[NN * M2];

// ---------------- helpers ----------------
// truncation-based 2-instruction split: hi = exact tf32 (low 13 bits masked),
// lo = exact fp32 residual (MMA hardware consumes only the tf32-significant bits)
__device__ __forceinline__ void split_tf(float v, unsigned& hi, unsigned& lo) {
    unsigned h = __float_as_uint(v) & 0xffffe000u;
    hi = h;
    lo = __float_as_uint(v - __uint_as_float(h));
}
__device__ __forceinline__ void mma8(float& d0, float& d1, float& d2, float& d3,
                                     unsigned a0, unsigned a1, unsigned a2, unsigned a3,
                                     unsigned b0, unsigned b1) {
    asm("mma.sync.aligned.m16n8k8.row.col.f32.tf32.tf32.f32 "
        "{%0,%1,%2,%3},{%4,%5,%6,%7},{%8,%9},{%0,%1,%2,%3};"
        : "+f"(d0), "+f"(d1), "+f"(d2), "+f"(d3)
        : "r"(a0), "r"(a1), "r"(a2), "r"(a3), "r"(b0), "r"(b1));
}
#define MMA3(ACC, AH0,AH1,AH2,AH3, AL0,AL1,AL2,AL3, BH0,BH1, BL0,BL1)             \
    do {                                                                           \
        mma8(ACC[0],ACC[1],ACC[2],ACC[3], AH0,AH1,AH2,AH3, BL0,BL1);               \
        mma8(ACC[0],ACC[1],ACC[2],ACC[3], AL0,AL1,AL2,AL3, BH0,BH1);               \
        mma8(ACC[0],ACC[1],ACC[2],ACC[3], AH0,AH1,AH2,AH3, BH0,BH1);               \
    } while (0)
#define MMA3S(ACC, ACG, AH0,AH1,AH2,AH3, AL0,AL1,AL2,AL3, BH0,BH1, BL0,BL1)       \
    do {                                                                           \
        mma8(ACG[0],ACG[1],ACG[2],ACG[3], AH0,AH1,AH2,AH3, BL0,BL1);               \
        mma8(ACG[0],ACG[1],ACG[2],ACG[3], AL0,AL1,AL2,AL3, BH0,BH1);               \
        mma8(ACC[0],ACC[1],ACC[2],ACC[3], AH0,AH1,AH2,AH3, BH0,BH1);               \
    } while (0)

__device__ __forceinline__ float ftanh(float x) {
    float e = __expf(2.f * x);
    return 1.f - __fdividef(2.f, e + 1.f);
}

// ---------------- DCT basis tables ----------------
__global__ void k_init() {
    int x = blockIdx.x, t = threadIdx.x;
    if (t < RR) {
        int k = (t < M1) ? t : (216 + t);
        int m = (k * x) % 510;
        float cv = (float)cospi((double)m / 255.0);
        float cx = (x == 0 || x == 255) ? 1.f : 2.f;
        g_F1[t * NN + x] = cx * cv;
        float ck = (k == 0 || k == 255) ? 1.f : 2.f;
        g_G1[x * RR + t] = ck * cv;
    }
    if (t < M2) {
        int m = (t * x) % 510;
        float cv = (float)cospi((double)m / 255.0);
        float cy = (x == 0 || x == 255) ? 1.f : 2.f;
        g_F2[t * NN + x] = cy * cv;
        float cs = (t == 0) ? 1.f : 2.f;
        g_G2[x * M2 + t] = cs * cv;
    }
}

// ---------------- spectral weight transpose ----------------
__global__ void k_wtrans(const float* __restrict__ w1, const float* __restrict__ w2) {
    __shared__ float tile[32][33];
    int l = blockIdx.z >> 1, half = blockIdx.z & 1;
    const float* src = (half ? w2 : w1) + (size_t)l * CC * CC * (M1 * M2);
    float* dst = g_Wm + ((size_t)l * MODES + half * 400) * (CC * CC);
    int col = blockIdx.x * 32 + threadIdx.x;
    int row = blockIdx.y * 32 + threadIdx.y;
    if (col < 400) tile[threadIdx.y][threadIdx.x] = src[(size_t)row * 400 + col];
    __syncthreads();
    int drow = blockIdx.x * 32 + threadIdx.y;
    int dcol = blockIdx.y * 32 + threadIdx.x;
    if (drow < 400) dst[(size_t)drow * 4096 + dcol] = tile[threadIdx.x][threadIdx.y];
}

// ---------------- fc0 ----------------
__global__ void k_fc0(const float* __restrict__ x, const float* __restrict__ w,
                      const float* __restrict__ bias) {
    __shared__ float sw[3][CC];
    __shared__ float sb[CC];
    int xi = blockIdx.x, b = blockIdx.y, y = threadIdx.x;
    if (y < CC) { sw[0][y] = w[y]; sw[1][y] = w[CC + y]; sw[2][y] = w[2 * CC + y]; sb[y] = bias[y]; }
    __syncthreads();
    const float* xp = x + (((size_t)b * NN + xi) * NN + y) * 3;
    float d0 = xp[0], d1 = xp[1], d2 = xp[2];
    float* hp = g_h + ((size_t)(b * CC) * NN + xi) * NN + y;
#pragma unroll
    for (int c = 0; c < CC; c++)
        hp[(size_t)c * (NN * NN)] = sb[c] + d0 * sw[0][c] + d1 * sw[1][c] + d2 * sw[2][c];
}

// ---------------- forward DCT stage 1' (y-first streaming, paired-y fragments) ----------
// t1p[row][s] = sum_y H[row][y] * F2[s][y].  Fragment k-slot t maps to y = k0+2(t&3)+(t>>2):
// A loads become float2 (adjacent y), B loads one uint4 (hi,lo pairs of y, y+1).
__global__ __launch_bounds__(256) void k_s1p() {
    extern __shared__ unsigned smu[];
    unsigned* sB = smu;                // [24][SBP] interleaved (hi,lo) by y
    int tid = threadIdx.x;
    int wid = tid >> 5, lane = tid & 31, gid = lane >> 2, tig = lane & 3;

    for (int idx = tid; idx < 24 * 256; idx += 256) {
        int n = idx >> 8, y = idx & 255;
        float v = (n < 20) ? g_F2[n * NN + y] : 0.f;
        split_tf(v, sB[n * SBP + 2 * y], sB[n * SBP + 2 * y + 1]);
    }
    __syncthreads();

    size_t row0 = (size_t)blockIdx.x * 128 + wid * 16;
    const float* A0 = g_h + (row0 + gid) * NN;
    const float* A1 = g_h + (row0 + gid + 8) * NN;

    float acc[3][4], acg[3][4];
#pragma unroll
    for (int i = 0; i < 3; i++) {
        acc[i][0] = acc[i][1] = acc[i][2] = acc[i][3] = 0.f;
        acg[i][0] = acg[i][1] = acg[i][2] = acg[i][3] = 0.f;
    }

#pragma unroll 4
    for (int k0 = 0; k0 < 256; k0 += 8) {
        float2 p0 = *(const float2*)&A0[k0 + 2 * tig];   // y = k0+2tig, +1
        float2 p1 = *(const float2*)&A1[k0 + 2 * tig];
        unsigned ah0, al0, ah1, al1, ah2, al2, ah3, al3;
        split_tf(p0.x, ah0, al0); split_tf(p1.x, ah1, al1);
        split_tf(p0.y, ah2, al2); split_tf(p1.y, ah3, al3);
#pragma unroll
        for (int nt = 0; nt < 3; nt++) {
            int n = nt * 8 + gid;
            uint4 bv = *(const uint4*)&sB[n * SBP + 2 * k0 + 4 * tig];
            // bv = (hi[y0], lo[y0], hi[y0+1], lo[y0+1]); slot tig -> y0, slot tig+4 -> y0+1
            MMA3S(acc[nt], acg[nt], ah0,ah1,ah2,ah3, al0,al1,al2,al3, bv.x, bv.z, bv.y, bv.w);
        }
    }

    float* t0 = g_t1p + (row0 + gid) * M2;
    float* t1 = g_t1p + (row0 + gid + 8) * M2;
#pragma unroll
    for (int nt = 0; nt < 3; nt++) {
        int c0 = nt * 8 + tig * 2;
        if (c0 < 20) {
            *(float2*)&t0[c0] = make_float2(acc[nt][0] + acg[nt][0], acc[nt][1] + acg[nt][1]);
            *(float2*)&t1[c0] = make_float2(acc[nt][2] + acg[nt][2], acc[nt][3] + acg[nt][3]);
        }
    }
}

// ---------------- forward DCT stage 2' (x contraction, exact fp32) ----------------
__global__ __launch_bounds__(256) void k_s2p() {
    __shared__ float sS[NN * M2];      // [x][s]
    int bc = blockIdx.x, t = threadIdx.x;
    const float4* tp = (const float4*)(g_t1p + (size_t)bc * NN * M2);
    for (int i = t; i < NN * 5; i += 256) ((float4*)sS)[i] = tp[i];
    __syncthreads();
    if (t < 200) {
        int a = t / 5, q = t % 5;
        float4 acc = make_float4(0.f, 0.f, 0.f, 0.f);
        const float* f1 = g_F1 + a * NN;
#pragma unroll 4
        for (int x = 0; x < NN; x++) {
            float f = __ldg(&f1[x]);
            float4 v = *(const float4*)&sS[x * M2 + 4 * q];
            acc.x += f * v.x; acc.y += f * v.y; acc.z += f * v.z; acc.w += f * v.w;
        }
        int m0 = a * M2 + 4 * q;
        g_spec[(size_t)(m0 + 0) * (BB * CC) + bc] = acc.x;
        g_spec[(size_t)(m0 + 1) * (BB * CC) + bc] = acc.y;
        g_spec[(size_t)(m0 + 2) * (BB * CC) + bc] = acc.z;
        g_spec[(size_t)(m0 + 3) * (BB * CC) + bc] = acc.w;
    }
}

// ---------------- per-mode channel mix (exact fp32) ----------------
__global__ __launch_bounds__(256) void k_mix(int l) {
    __shared__ float sW[CC * CC];
    __shared__ float sS[BB * CC];
    int m = blockIdx.x, t = threadIdx.x;
    const float* Wp = g_Wm + ((size_t)l * MODES + m) * (CC * CC);
    for (int i = t; i < CC * CC; i += 256) sW[i] = Wp[i];
    for (int i = t; i < BB * CC; i += 256) sS[i] = g_spec[(size_t)m * (BB * CC) + i];
    __syncthreads();
#pragma unroll
    for (int k = 0; k < 2; k++) {
        int idx = t + k * 256;
        int b = idx >> 6, o = idx & 63;
        float acc = 0.f;
#pragma unroll
        for (int i = 0; i < CC; i++) acc += sS[b * CC + i] * sW[i * CC + o];
        g_spec2[(size_t)(b * CC + o) * MODES + m] = acc;
    }
}

// ---------------- inverse stage 1 (exact fp32) ----------------
__global__ __launch_bounds__(256) void k_istage1() {
    __shared__ float sS[MODES];
    int bo = blockIdx.x, x = threadIdx.x;
    for (int i = x; i < MODES; i += 256) sS[i] = g_spec2[(size_t)bo * MODES + i];
    __syncthreads();
    float g1r[RR];
    const float4* gp = (const float4*)(g_G1 + x * RR);
#pragma unroll
    for (int j = 0; j < RR / 4; j++) {
        float4 v = gp[j];
        g1r[4 * j] = v.x; g1r[4 * j + 1] = v.y; g1r[4 * j + 2] = v.z; g1r[4 * j + 3] = v.w;
    }
    float acc[M2];
#pragma unroll
    for (int s = 0; s < M2; s++) acc[s] = 0.f;
#pragma unroll 4
    for (int r = 0; r < RR; r++) {
        float g = g1r[r];
#pragma unroll
        for (int s = 0; s < M2; s++) acc[s] += g * sS[r * M2 + s];
    }
    float* tp = g_t2 + ((size_t)bo * NN + x) * M2;
#pragma unroll
    for (int s = 0; s < M2; s++) tp[s] = acc[s];
}

// ---------------- fused layer update (pre-split interleaved B, LDS.64, in place) ---------
// OUT(64x256) = CW(64x64)*H(64x256) + T2(64x24)*G2T(24x256) + bias, [tanh]
__global__ __launch_bounds__(512, 2) void k_ilayer_mma(const float* __restrict__ conv_w,
                                                       const float* __restrict__ conv_b,
                                                       int l, int do_tanh) {
    extern __shared__ unsigned smu[];
    float* sA1 = (float*)smu;                 // [64][AP] conv weights (fp32, inline split)
    float* sA2 = sA1 + 64 * AP;               // [64][28] T2 (fp32, inline split)
    unsigned* sB = (unsigned*)(sA2 + 64 * 28);   // [24][IBP] interleaved (hi,lo) by n
    int x = blockIdx.x, b = blockIdx.y, tid = threadIdx.x;
    int wid = tid >> 5, lane = tid & 31, gid = lane >> 2, tig = lane & 3;
    int mt = wid & 3, nh = wid >> 2;
    int obase = mt * 16, ybase = nh * 64;

    const float* cw = conv_w + (size_t)l * CC * CC;
    for (int idx = tid; idx < 64 * AP; idx += 512) {
        int o = idx / AP, i = idx % AP;
        sA1[idx] = (i < 64) ? cw[o * 64 + i] : 0.f;
    }
    for (int idx = tid; idx < 64 * 28; idx += 512) {
        int o = idx / 28, s = idx % 28;
        sA2[idx] = (s < 20) ? g_t2[(((size_t)(b * 64 + o)) * NN + x) * M2 + s] : 0.f;
    }

    float bias0 = __ldg(&conv_b[l * 64 + obase + gid]);
    float bias1 = __ldg(&conv_b[l * 64 + obase + gid + 8]);
    float acc[8][4];
#pragma unroll
    for (int nt = 0; nt < 8; nt++) { acc[nt][0] = acc[nt][1] = bias0; acc[nt][2] = acc[nt][3] = bias1; }

    // ---- DCT term: B = G2T (24 rows), pre-split interleaved ----
    __syncthreads();
    for (int idx = tid; idx < 24 * 256; idx += 512) {
        int s = idx >> 8, y = idx & 255;
        float v = (s < 20) ? g_G2[y * M2 + s] : 0.f;
        split_tf(v, sB[s * IBP + 2 * y], sB[s * IBP + 2 * y + 1]);
    }
    __syncthreads();
#pragma unroll
    for (int ks = 0; ks < 3; ks++) {
        int k0 = ks * 8;
        unsigned ah0, al0, ah1, al1, ah2, al2, ah3, al3;
        split_tf(sA2[(obase + gid) * 28 + k0 + tig], ah0, al0);
        split_tf(sA2[(obase + gid + 8) * 28 + k0 + tig], ah1, al1);
        split_tf(sA2[(obase + gid) * 28 + k0 + tig + 4], ah2, al2);
        split_tf(sA2[(obase + gid + 8) * 28 + k0 + tig + 4], ah3, al3);
#pragma unroll
        for (int nt = 0; nt < 8; nt++) {
            int n = ybase + nt * 8 + gid;
            uint2 b0 = *(const uint2*)&sB[(k0 + tig) * IBP + 2 * n];
            uint2 b1 = *(const uint2*)&sB[(k0 + tig + 4) * IBP + 2 * n];
            MMA3(acc[nt], ah0,ah1,ah2,ah3, al0,al1,al2,al3, b0.x, b1.x, b0.y, b1.y);
        }
    }

    // ---- conv term: K = 64 in four 16-row chunks, H pre-split interleaved ----
    for (int hc = 0; hc < 4; hc++) {
        __syncthreads();
        for (int idx = tid; idx < 16 * 64; idx += 512) {
            int i = idx >> 6, q = idx & 63;
            float4 v = *(const float4*)&g_h[(((size_t)(b * 64 + hc * 16 + i)) * NN + x) * NN + q * 4];
            unsigned h0, l0, h1, l1, h2, l2, h3, l3;
            split_tf(v.x, h0, l0); split_tf(v.y, h1, l1);
            split_tf(v.z, h2, l2); split_tf(v.w, h3, l3);
            *(uint4*)&sB[i * IBP + 8 * q]     = make_uint4(h0, l0, h1, l1);
            *(uint4*)&sB[i * IBP + 8 * q + 4] = make_uint4(h2, l2, h3, l3);
        }
        __syncthreads();
#pragma unroll
        for (int ks = 0; ks < 2; ks++) {
            int k0 = ks * 8;
            int ca = hc * 16 + k0 + tig;
            unsigned ah0, al0, ah1, al1, ah2, al2, ah3, al3;
            split_tf(sA1[(obase + gid) * AP + ca], ah0, al0);
            split_tf(sA1[(obase + gid + 8) * AP + ca], ah1, al1);
            split_tf(sA1[(obase + gid) * AP + ca + 4], ah2, al2);
            split_tf(sA1[(obase + gid + 8) * AP + ca + 4], ah3, al3);
#pragma unroll
            for (int nt = 0; nt < 8; nt++) {
                int n = ybase + nt * 8 + gid;
                uint2 b0 = *(const uint2*)&sB[(k0 + tig) * IBP + 2 * n];
                uint2 b1 = *(const uint2*)&sB[(k0 + tig + 4) * IBP + 2 * n];
                MMA3(acc[nt], ah0,ah1,ah2,ah3, al0,al1,al2,al3, b0.x, b1.x, b0.y, b1.y);
            }
        }
    }

    int r0 = obase + gid, r1 = r0 + 8;
    float* h0 = &g_h[(((size_t)(b * 64 + r0)) * NN + x) * NN];
    float* h1 = &g_h[(((size_t)(b * 64 + r1)) * NN + x) * NN];
#pragma unroll
    for (int nt = 0; nt < 8; nt++) {
        int y0 = ybase + nt * 8 + tig * 2;
        float d0 = acc[nt][0], d1 = acc[nt][1], d2 = acc[nt][2], d3 = acc[nt][3];
        if (do_tanh) { d0 = ftanh(d0); d1 = ftanh(d1); d2 = ftanh(d2); d3 = ftanh(d3); }
        *(float2*)&h0[y0] = make_float2(d0, d1);
        *(float2*)&h1[y0] = make_float2(d2, d3);
    }
}

// ---------------- fc1 (tanh) + fc2 fused (pre-split interleaved B, LDS.64) ----------------
__global__ __launch_bounds__(512, 2) void k_fc12_mma(const float* __restrict__ w1,
                                                     const float* __restrict__ b1,
                                                     const float* __restrict__ w2,
                                                     const float* __restrict__ b2,
                                                     float* __restrict__ out) {
    extern __shared__ unsigned smu[];
    float* sA = (float*)smu;                      // [128][AP] fp32
    unsigned* sB = (unsigned*)(sA + 128 * AP);    // [32][IBP] interleaved
    float* sred = (float*)(sB + 32 * IBP);        // [256]
    float* sb1  = sred + 256;                     // [128]
    float* sw2  = sb1 + 128;                      // [128]
    int x = blockIdx.x, b = blockIdx.y, tid = threadIdx.x;
    int wid = tid >> 5, lane = tid & 31, gid = lane >> 2, tig = lane & 3;
    int mt = wid & 7, nh = wid >> 3;
    int fbase = mt * 16, ybase = nh * 128;

    for (int idx = tid; idx < 128 * AP; idx += 512) {
        int f = idx / AP, c = idx % AP;
        sA[idx] = (c < 64) ? w1[c * FCN + f] : 0.f;
    }
    if (tid < 256) sred[tid] = 0.f;
    if (tid < 128) { sb1[tid] = b1[tid]; sw2[tid] = w2[tid]; }
    __syncthreads();

    float bias0 = sb1[fbase + gid], bias1 = sb1[fbase + gid + 8];
    float w20 = sw2[fbase + gid], w21 = sw2[fbase + gid + 8];
    float acc[16][4];
#pragma unroll
    for (int nt = 0; nt < 16; nt++) { acc[nt][0] = acc[nt][1] = bias0; acc[nt][2] = acc[nt][3] = bias1; }

    for (int hc = 0; hc < 2; hc++) {
        __syncthreads();
        for (int idx = tid; idx < 32 * 64; idx += 512) {
            int i = idx >> 6, q = idx & 63;
            float4 v = *(const float4*)&g_h[(((size_t)(b * 64 + hc * 32 + i)) * NN + x) * NN + q * 4];
            unsigned h0, l0, h1, l1, h2, l2, h3, l3;
            split_tf(v.x, h0, l0); split_tf(v.y, h1, l1);
            split_tf(v.z, h2, l2); split_tf(v.w, h3, l3);
            *(uint4*)&sB[i * IBP + 8 * q]     = make_uint4(h0, l0, h1, l1);
            *(uint4*)&sB[i * IBP + 8 * q + 4] = make_uint4(h2, l2, h3, l3);
        }
        __syncthreads();
#pragma unroll
        for (int ks = 0; ks < 4; ks++) {
            int k0 = ks * 8;
            int ca = hc * 32 + k0 + tig;
            unsigned ah0, al0, ah1, al1, ah2, al2, ah3, al3;
            split_tf(sA[(fbase + gid) * AP + ca], ah0, al0);
            split_tf(sA[(fbase + gid + 8) * AP + ca], ah1, al1);
            split_tf(sA[(fbase + gid) * AP + ca + 4], ah2, al2);
            split_tf(sA[(fbase + gid + 8) * AP + ca + 4], ah3, al3);
#pragma unroll
            for (int nt = 0; nt < 16; nt++) {
                int n = ybase + nt * 8 + gid;
                uint2 b0 = *(const uint2*)&sB[(k0 + tig) * IBP + 2 * n];
                uint2 b1 = *(const uint2*)&sB[(k0 + tig + 4) * IBP + 2 * n];
                MMA3(acc[nt], ah0,ah1,ah2,ah3, al0,al1,al2,al3, b0.x, b1.x, b0.y, b1.y);
            }
        }
    }

#pragma unroll
    for (int nt = 0; nt < 16; nt++) {
        float p0 = ftanh(acc[nt][0]) * w20 + ftanh(acc[nt][2]) * w21;
        float p1 = ftanh(acc[nt][1]) * w20 + ftanh(acc[nt][3]) * w21;
#pragma unroll
        for (int m = 4; m < 32; m <<= 1) {
            p0 += __shfl_xor_sync(0xffffffffu, p0, m);
            p1 += __shfl_xor_sync(0xffffffffu, p1, m);
        }
        if (lane < 4) {
            int y0 = ybase + nt * 8 + lane * 2;
            atomicAdd(&sred[y0], p0);
            atomicAdd(&sred[y0 + 1], p1);
        }
    }
    __syncthreads();
    if (tid < 256)
        out[((size_t)b * NN + x) * NN + tid] = sred[tid] + __ldg(&b2[0]);
}

// ---------------- launch ----------------
extern "C" void kernel_launch(void* const* d_in, const int* in_sizes, int n_in,
                              void* d_out, int out_size) {
    const float* x      = (const float*)d_in[0];
    const float* fc0_w  = (const float*)d_in[1];
    const float* fc0_b  = (const float*)d_in[2];
    const float* sp_w1  = (const float*)d_in[3];
    const float* sp_w2  = (const float*)d_in[4];
    const float* conv_w = (const float*)d_in[5];
    const float* conv_b = (const float*)d_in[6];
    const float* fc1_w  = (const float*)d_in[7];
    const float* fc1_b  = (const float*)d_in[8];
    const float* fc2_w  = (const float*)d_in[9];
    const float* fc2_b  = (const float*)d_in[10];
    float* out = (float*)d_out;

    const int SM_S1P    = 24 * SBP * 4;                                          // 50688
    const int SM_ILAYER = (64 * AP + 64 * 28) * 4 + 24 * IBP * 4;                // 74496
    const int SM_FC12   = 128 * AP * 4 + 32 * IBP * 4 + (256 + 128 + 128) * 4;   // 103424

    cudaFuncSetAttribute(k_s1p, cudaFuncAttributeMaxDynamicSharedMemorySize, SM_S1P);
    cudaFuncSetAttribute(k_ilayer_mma, cudaFuncAttributeMaxDynamicSharedMemorySize, SM_ILAYER);
    cudaFuncSetAttribute(k_fc12_mma, cudaFuncAttributeMaxDynamicSharedMemorySize, SM_FC12);

    k_init<<<NN, 256>>>();
    k_wtrans<<<dim3(13, 128, LL * 2), dim3(32, 32)>>>(sp_w1, sp_w2);
    k_fc0<<<dim3(NN, BB), 256>>>(x, fc0_w, fc0_b);

    for (int l = 0; l < LL; l++) {
        k_s1p<<<(BB * CC * NN) / 128, 256, SM_S1P>>>();
        k_s2p<<<BB * CC, 256>>>();
        k_mix<<<MODES, 256>>>(l);
        k_istage1<<<BB * CC, 256>>>();
        k_ilayer_mma<<<dim3(NN, BB), 512, SM_ILAYER>>>(conv_w, conv_b, l, (l != LL - 1) ? 1 : 0);
    }

    k_fc12_mma<<<dim3(NN, BB), 512, SM_FC12>>>(fc1_w, fc1_b, fc2_w, fc2_b, out);
}

// round 16
// speedup vs baseline: 1.0869x; 1.0653x over previous
#include <cuda_runtime.h>
#include <math.h>

#define BB 8
#define CC 64
#define NN 256
#define M1 20
#define M2 20
#define RR 40
#define MODES 800
#define LL 3
#define FCN 128
#define AP 68           // A-matrix smem row pitch (floats)
#define SBP 528         // s1p B pitch (words)
#define IBP 520         // ilayer/fc12 B pitch (words)
#define PBP 56          // s2p B pitch (words), 56 % 32 == 24 -> conflict-free uint2
#define F1P 260         // s2p F1 pitch

// ---------------- device scratch ----------------
__device__ float g_h[BB * CC * NN * NN];
__device__ float g_t1p[BB * CC * NN * M2];
__device__ float g_spec[MODES * BB * CC];
__device__ float g_spec2[BB * CC * MODES];
__device__ float g_t2[BB * CC * NN * M2];
__device__ float g_Wm[LL * MODES * CC * CC];
__device__ float g_F1[RR * NN];
__device__ float g_F2[M2 * NN];
__device__ float g_G1[NN * RR];
__device__ float g_G2[NN * M2];

// ---------------- helpers ----------------
__device__ __forceinline__ void split_tf(float v, unsigned& hi, unsigned& lo) {
    unsigned h = __float_as_uint(v) & 0xffffe000u;
    hi = h;
    lo = __float_as_uint(v - __uint_as_float(h));
}
__device__ __forceinline__ void mma8(float& d0, float& d1, float& d2, float& d3,
                                     unsigned a0, unsigned a1, unsigned a2, unsigned a3,
                                     unsigned b0, unsigned b1) {
    asm("mma.sync.aligned.m16n8k8.row.col.f32.tf32.tf32.f32 "
        "{%0,%1,%2,%3},{%4,%5,%6,%7},{%8,%9},{%0,%1,%2,%3};"
        : "+f"(d0), "+f"(d1), "+f"(d2), "+f"(d3)
        : "r"(a0), "r"(a1), "r"(a2), "r"(a3), "r"(b0), "r"(b1));
}
#define MMA3(ACC, AH0,AH1,AH2,AH3, AL0,AL1,AL2,AL3, BH0,BH1, BL0,BL1)             \
    do {                                                                           \
        mma8(ACC[0],ACC[1],ACC[2],ACC[3], AH0,AH1,AH2,AH3, BL0,BL1);               \
        mma8(ACC[0],ACC[1],ACC[2],ACC[3], AL0,AL1,AL2,AL3, BH0,BH1);               \
        mma8(ACC[0],ACC[1],ACC[2],ACC[3], AH0,AH1,AH2,AH3, BH0,BH1);               \
    } while (0)
#define MMA3S(ACC, ACG, AH0,AH1,AH2,AH3, AL0,AL1,AL2,AL3, BH0,BH1, BL0,BL1)       \
    do {                                                                           \
        mma8(ACG[0],ACG[1],ACG[2],ACG[3], AH0,AH1,AH2,AH3, BL0,BL1);               \
        mma8(ACG[0],ACG[1],ACG[2],ACG[3], AL0,AL1,AL2,AL3, BH0,BH1);               \
        mma8(ACC[0],ACC[1],ACC[2],ACC[3], AH0,AH1,AH2,AH3, BH0,BH1);               \
    } while (0)

__device__ __forceinline__ float ftanh(float x) {
    float e = __expf(2.f * x);
    return 1.f - __fdividef(2.f, e + 1.f);
}
__device__ __forceinline__ void store_frag(unsigned* dst, int i, int q, float4 v) {
    unsigned h0, l0, h1, l1, h2, l2, h3, l3;
    split_tf(v.x, h0, l0); split_tf(v.y, h1, l1);
    split_tf(v.z, h2, l2); split_tf(v.w, h3, l3);
    *(uint4*)&dst[i * IBP + 8 * q]     = make_uint4(h0, l0, h1, l1);
    *(uint4*)&dst[i * IBP + 8 * q + 4] = make_uint4(h2, l2, h3, l3);
}

// ---------------- DCT basis tables ----------------
__global__ void k_init() {
    int x = blockIdx.x, t = threadIdx.x;
    if (t < RR) {
        int k = (t < M1) ? t : (216 + t);
        int m = (k * x) % 510;
        float cv = (float)cospi((double)m / 255.0);
        float cx = (x == 0 || x == 255) ? 1.f : 2.f;
        g_F1[t * NN + x] = cx * cv;
        float ck = (k == 0 || k == 255) ? 1.f : 2.f;
        g_G1[x * RR + t] = ck * cv;
    }
    if (t < M2) {
        int m = (t * x) % 510;
        float cv = (float)cospi((double)m / 255.0);
        float cy = (x == 0 || x == 255) ? 1.f : 2.f;
        g_F2[t * NN + x] = cy * cv;
        float cs = (t == 0) ? 1.f : 2.f;
        g_G2[x * M2 + t] = cs * cv;
    }
}

// ---------------- spectral weight transpose ----------------
__global__ void k_wtrans(const float* __restrict__ w1, const float* __restrict__ w2) {
    __shared__ float tile[32][33];
    int l = blockIdx.z >> 1, half = blockIdx.z & 1;
    const float* src = (half ? w2 : w1) + (size_t)l * CC * CC * (M1 * M2);
    float* dst = g_Wm + ((size_t)l * MODES + half * 400) * (CC * CC);
    int col = blockIdx.x * 32 + threadIdx.x;
    int row = blockIdx.y * 32 + threadIdx.y;
    if (col < 400) tile[threadIdx.y][threadIdx.x] = src[(size_t)row * 400 + col];
    __syncthreads();
    int drow = blockIdx.x * 32 + threadIdx.y;
    int dcol = blockIdx.y * 32 + threadIdx.x;
    if (drow < 400) dst[(size_t)drow * 4096 + dcol] = tile[threadIdx.x][threadIdx.y];
}

// ---------------- fc0 ----------------
__global__ void k_fc0(const float* __restrict__ x, const float* __restrict__ w,
                      const float* __restrict__ bias) {
    __shared__ float sw[3][CC];
    __shared__ float sb[CC];
    int xi = blockIdx.x, b = blockIdx.y, y = threadIdx.x;
    if (y < CC) { sw[0][y] = w[y]; sw[1][y] = w[CC + y]; sw[2][y] = w[2 * CC + y]; sb[y] = bias[y]; }
    __syncthreads();
    const float* xp = x + (((size_t)b * NN + xi) * NN + y) * 3;
    float d0 = xp[0], d1 = xp[1], d2 = xp[2];
    float* hp = g_h + ((size_t)(b * CC) * NN + xi) * NN + y;
#pragma unroll
    for (int c = 0; c < CC; c++)
        hp[(size_t)c * (NN * NN)] = sb[c] + d0 * sw[0][c] + d1 * sw[1][c] + d2 * sw[2][c];
}

// ---------------- forward DCT stage 1' (unchanged from R15) ----------
__global__ __launch_bounds__(256) void k_s1p() {
    extern __shared__ unsigned smu[];
    unsigned* sB = smu;                // [24][SBP]
    int tid = threadIdx.x;
    int wid = tid >> 5, lane = tid & 31, gid = lane >> 2, tig = lane & 3;

    for (int idx = tid; idx < 24 * 256; idx += 256) {
        int n = idx >> 8, y = idx & 255;
        float v = (n < 20) ? g_F2[n * NN + y] : 0.f;
        split_tf(v, sB[n * SBP + 2 * y], sB[n * SBP + 2 * y + 1]);
    }
    __syncthreads();

    size_t row0 = (size_t)blockIdx.x * 128 + wid * 16;
    const float* A0 = g_h + (row0 + gid) * NN;
    const float* A1 = g_h + (row0 + gid + 8) * NN;

    float acc[3][4], acg[3][4];
#pragma unroll
    for (int i = 0; i < 3; i++) {
        acc[i][0] = acc[i][1] = acc[i][2] = acc[i][3] = 0.f;
        acg[i][0] = acg[i][1] = acg[i][2] = acg[i][3] = 0.f;
    }

#pragma unroll 4
    for (int k0 = 0; k0 < 256; k0 += 8) {
        float2 p0 = *(const float2*)&A0[k0 + 2 * tig];
        float2 p1 = *(const float2*)&A1[k0 + 2 * tig];
        unsigned ah0, al0, ah1, al1, ah2, al2, ah3, al3;
        split_tf(p0.x, ah0, al0); split_tf(p1.x, ah1, al1);
        split_tf(p0.y, ah2, al2); split_tf(p1.y, ah3, al3);
#pragma unroll
        for (int nt = 0; nt < 3; nt++) {
            int n = nt * 8 + gid;
            uint4 bv = *(const uint4*)&sB[n * SBP + 2 * k0 + 4 * tig];
            MMA3S(acc[nt], acg[nt], ah0,ah1,ah2,ah3, al0,al1,al2,al3, bv.x, bv.z, bv.y, bv.w);
        }
    }

    float* t0 = g_t1p + (row0 + gid) * M2;
    float* t1 = g_t1p + (row0 + gid + 8) * M2;
#pragma unroll
    for (int nt = 0; nt < 3; nt++) {
        int c0 = nt * 8 + tig * 2;
        if (c0 < 20) {
            *(float2*)&t0[c0] = make_float2(acc[nt][0] + acg[nt][0], acc[nt][1] + acg[nt][1]);
            *(float2*)&t1[c0] = make_float2(acc[nt][2] + acg[nt][2], acc[nt][3] + acg[nt][3]);
        }
    }
}

// ---------------- forward DCT stage 2' (MMA): spec = F1(40x256) * t1p[bc](256x20) ---------
// 6 active warps: mt in {0,1,2} M-tiles, kh in {0,1} K-halves; smem reduction of halves.
__global__ __launch_bounds__(256) void k_s2p_mma() {
    extern __shared__ unsigned smu[];
    float* sA = (float*)smu;                 // [48][F1P] F1 fp32
    unsigned* sB = smu + 48 * F1P;           // [256][PBP] interleaved (hi,lo)
    int bc = blockIdx.x, tid = threadIdx.x;
    int wid = tid >> 5, lane = tid & 31, gid = lane >> 2, tig = lane & 3;

    for (int idx = tid; idx < 48 * 256; idx += 256) {
        int r = idx >> 8, xx = idx & 255;
        sA[r * F1P + xx] = (r < RR) ? g_F1[r * NN + xx] : 0.f;
    }
    const float* tb = g_t1p + (size_t)bc * (NN * M2);
    for (int idx = tid; idx < 256 * 24; idx += 256) {
        int xx = idx / 24, s = idx % 24;
        float v = (s < 20) ? tb[xx * 20 + s] : 0.f;
        split_tf(v, sB[xx * PBP + 2 * s], sB[xx * PBP + 2 * s + 1]);
    }
    __syncthreads();

    float acc[3][4];
#pragma unroll
    for (int i = 0; i < 3; i++) { acc[i][0] = acc[i][1] = acc[i][2] = acc[i][3] = 0.f; }

    int mt = wid % 3, kh = wid / 3;      // valid for wid < 6
    if (wid < 6) {
        int mtb = mt * 16;
#pragma unroll 4
        for (int ks = 0; ks < 16; ks++) {
            int k0 = kh * 128 + ks * 8;
            unsigned ah0, al0, ah1, al1, ah2, al2, ah3, al3;
            split_tf(sA[(mtb + gid) * F1P + k0 + tig], ah0, al0);
            split_tf(sA[(mtb + gid + 8) * F1P + k0 + tig], ah1, al1);
            split_tf(sA[(mtb + gid) * F1P + k0 + tig + 4], ah2, al2);
            split_tf(sA[(mtb + gid + 8) * F1P + k0 + tig + 4], ah3, al3);
#pragma unroll
            for (int nt = 0; nt < 3; nt++) {
                int n = nt * 8 + gid;
                uint2 b0 = *(const uint2*)&sB[(k0 + tig) * PBP + 2 * n];
                uint2 b1 = *(const uint2*)&sB[(k0 + tig + 4) * PBP + 2 * n];
                MMA3(acc[nt], ah0,ah1,ah2,ah3, al0,al1,al2,al3, b0.x, b1.x, b0.y, b1.y);
            }
        }
    }
    __syncthreads();
    float* red = (float*)smu;            // [2][48][24] reuse sA region
    if (wid < 6) {
        int mtb = mt * 16;
#pragma unroll
        for (int nt = 0; nt < 3; nt++) {
            int c0 = nt * 8 + tig * 2;
            int r0 = mtb + gid, r1 = r0 + 8;
            red[kh * 1152 + r0 * 24 + c0]     = acc[nt][0];
            red[kh * 1152 + r0 * 24 + c0 + 1] = acc[nt][1];
            red[kh * 1152 + r1 * 24 + c0]     = acc[nt][2];
            red[kh * 1152 + r1 * 24 + c0 + 1] = acc[nt][3];
        }
    }
    __syncthreads();
    for (int idx = tid; idx < 48 * 24; idx += 256) {
        int r = idx / 24, s = idx % 24;
        if (r < RR && s < 20)
            g_spec[(size_t)(r * M2 + s) * (BB * CC) + bc] = red[idx] + red[1152 + idx];
    }
}

// ---------------- per-mode channel mix (exact fp32, float4 staging, dual chains) --------
__global__ __launch_bounds__(256) void k_mix(int l) {
    __shared__ float sW[CC * CC];
    __shared__ float sS[BB * CC];
    int m = blockIdx.x, t = threadIdx.x;
    const float4* Wp = (const float4*)(g_Wm + ((size_t)l * MODES + m) * (CC * CC));
#pragma unroll
    for (int j = 0; j < 4; j++) ((float4*)sW)[t + j * 256] = Wp[t + j * 256];
    if (t < 128) ((float4*)sS)[t] = ((const float4*)(g_spec + (size_t)m * (BB * CC)))[t];
    __syncthreads();
#pragma unroll
    for (int k = 0; k < 2; k++) {
        int idx = t + k * 256;
        int b = idx >> 6, o = idx & 63;
        float a0 = 0.f, a1 = 0.f;
#pragma unroll
        for (int i = 0; i < 32; i++) a0 += sS[b * CC + i] * sW[i * CC + o];
#pragma unroll
        for (int i = 32; i < 64; i++) a1 += sS[b * CC + i] * sW[i * CC + o];
        g_spec2[(size_t)(b * CC + o) * MODES + m] = a0 + a1;
    }
}

// ---------------- inverse stage 1 (exact fp32) ----------------
__global__ __launch_bounds__(256) void k_istage1() {
    __shared__ float sS[MODES];
    int bo = blockIdx.x, x = threadIdx.x;
    for (int i = x; i < MODES; i += 256) sS[i] = g_spec2[(size_t)bo * MODES + i];
    __syncthreads();
    float g1r[RR];
    const float4* gp = (const float4*)(g_G1 + x * RR);
#pragma unroll
    for (int j = 0; j < RR / 4; j++) {
        float4 v = gp[j];
        g1r[4 * j] = v.x; g1r[4 * j + 1] = v.y; g1r[4 * j + 2] = v.z; g1r[4 * j + 3] = v.w;
    }
    float acc[M2];
#pragma unroll
    for (int s = 0; s < M2; s++) acc[s] = 0.f;
#pragma unroll 4
    for (int r = 0; r < RR; r++) {
        float g = g1r[r];
#pragma unroll
        for (int s = 0; s < M2; s++) acc[s] += g * sS[r * M2 + s];
    }
    float* tp = g_t2 + ((size_t)bo * NN + x) * M2;
#pragma unroll
    for (int s = 0; s < M2; s++) tp[s] = acc[s];
}

// ---------------- fused layer update (double-buffered H chunks, in place) ---------
__global__ __launch_bounds__(512, 2) void k_ilayer_mma(const float* __restrict__ conv_w,
                                                       const float* __restrict__ conv_b,
                                                       int l, int do_tanh) {
    extern __shared__ unsigned smu[];
    float* sA1 = (float*)smu;                    // [64][AP] conv weights fp32
    float* sA2 = sA1 + 64 * AP;                  // [64][28] T2 fp32
    unsigned* sB  = (unsigned*)(sA2 + 64 * 28);  // [24][IBP]: G2, then odd H chunks
    unsigned* sB2 = sB + 24 * IBP;               // [16][IBP]: even H chunks
    int x = blockIdx.x, b = blockIdx.y, tid = threadIdx.x;
    int wid = tid >> 5, lane = tid & 31, gid = lane >> 2, tig = lane & 3;
    int mt = wid & 3, nh = wid >> 2;
    int obase = mt * 16, ybase = nh * 64;

    const float* cw = conv_w + (size_t)l * CC * CC;
    for (int idx = tid; idx < 64 * AP; idx += 512) {
        int o = idx / AP, i = idx % AP;
        sA1[idx] = (i < 64) ? cw[o * 64 + i] : 0.f;
    }
    for (int idx = tid; idx < 64 * 28; idx += 512) {
        int o = idx / 28, s = idx % 28;
        sA2[idx] = (s < 20) ? g_t2[(((size_t)(b * 64 + o)) * NN + x) * M2 + s] : 0.f;
    }
    for (int idx = tid; idx < 24 * 256; idx += 512) {
        int s = idx >> 8, y = idx & 255;
        float v = (s < 20) ? g_G2[y * M2 + s] : 0.f;
        split_tf(v, sB[s * IBP + 2 * y], sB[s * IBP + 2 * y + 1]);
    }
    __syncthreads();

    float bias0 = __ldg(&conv_b[l * 64 + obase + gid]);
    float bias1 = __ldg(&conv_b[l * 64 + obase + gid + 8]);
    float acc[8][4];
#pragma unroll
    for (int nt = 0; nt < 8; nt++) { acc[nt][0] = acc[nt][1] = bias0; acc[nt][2] = acc[nt][3] = bias1; }

    const float* hbase = &g_h[((size_t)(b * 64) * NN + x) * NN];
    int si0 = tid >> 6, sq0 = tid & 63;          // staging element 0 (idx = tid)
    int si1 = (tid + 512) >> 6, sq1 = (tid + 512) & 63;

    // prefetch chunk 0 (rows 0..15) while computing DCT term
    float4 v0 = *(const float4*)&hbase[(size_t)si0 * (NN * NN) + sq0 * 4];
    float4 v1 = *(const float4*)&hbase[(size_t)si1 * (NN * NN) + sq1 * 4];

    // ---- DCT term: B = G2T in sB ----
#pragma unroll
    for (int ks = 0; ks < 3; ks++) {
        int k0 = ks * 8;
        unsigned ah0, al0, ah1, al1, ah2, al2, ah3, al3;
        split_tf(sA2[(obase + gid) * 28 + k0 + tig], ah0, al0);
        split_tf(sA2[(obase + gid + 8) * 28 + k0 + tig], ah1, al1);
        split_tf(sA2[(obase + gid) * 28 + k0 + tig + 4], ah2, al2);
        split_tf(sA2[(obase + gid + 8) * 28 + k0 + tig + 4], ah3, al3);
#pragma unroll
        for (int nt = 0; nt < 8; nt++) {
            int n = ybase + nt * 8 + gid;
            uint2 b0 = *(const uint2*)&sB[(k0 + tig) * IBP + 2 * n];
            uint2 b1 = *(const uint2*)&sB[(k0 + tig + 4) * IBP + 2 * n];
            MMA3(acc[nt], ah0,ah1,ah2,ah3, al0,al1,al2,al3, b0.x, b1.x, b0.y, b1.y);
        }
    }
    __syncthreads();               // G2 reads done; store chunk 0 into sB2
    store_frag(sB2, si0, sq0, v0);
    store_frag(sB2, si1, sq1, v1);
    __syncthreads();

    // ---- conv term: 4 chunks of 16 rows, double-buffered: even->sB2, odd->sB ----
    for (int hc = 0; hc < 4; hc++) {
        if (hc < 3) {              // prefetch next chunk
            const float* hb = hbase + (size_t)((hc + 1) * 16) * (NN * NN);
            v0 = *(const float4*)&hb[(size_t)si0 * (NN * NN) + sq0 * 4];
            v1 = *(const float4*)&hb[(size_t)si1 * (NN * NN) + sq1 * 4];
        }
        const unsigned* bufc = (hc & 1) ? sB : sB2;
#pragma unroll
        for (int ks = 0; ks < 2; ks++) {
            int k0 = ks * 8;
            int ca = hc * 16 + k0 + tig;
            unsigned ah0, al0, ah1, al1, ah2, al2, ah3, al3;
            split_tf(sA1[(obase + gid) * AP + ca], ah0, al0);
            split_tf(sA1[(obase + gid + 8) * AP + ca], ah1, al1);
            split_tf(sA1[(obase + gid) * AP + ca + 4], ah2, al2);
            split_tf(sA1[(obase + gid + 8) * AP + ca + 4], ah3, al3);
#pragma unroll
            for (int nt = 0; nt < 8; nt++) {
                int n = ybase + nt * 8 + gid;
                uint2 b0 = *(const uint2*)&bufc[(k0 + tig) * IBP + 2 * n];
                uint2 b1 = *(const uint2*)&bufc[(k0 + tig + 4) * IBP + 2 * n];
                MMA3(acc[nt], ah0,ah1,ah2,ah3, al0,al1,al2,al3, b0.x, b1.x, b0.y, b1.y);
            }
        }
        if (hc < 3) {
            unsigned* dst = ((hc + 1) & 1) ? sB : sB2;
            store_frag(dst, si0, sq0, v0);
            store_frag(dst, si1, sq1, v1);
        }
        __syncthreads();
    }

    int r0 = obase + gid, r1 = r0 + 8;
    float* h0 = &g_h[(((size_t)(b * 64 + r0)) * NN + x) * NN];
    float* h1 = &g_h[(((size_t)(b * 64 + r1)) * NN + x) * NN];
#pragma unroll
    for (int nt = 0; nt < 8; nt++) {
        int y0 = ybase + nt * 8 + tig * 2;
        float d0 = acc[nt][0], d1 = acc[nt][1], d2 = acc[nt][2], d3 = acc[nt][3];
        if (do_tanh) { d0 = ftanh(d0); d1 = ftanh(d1); d2 = ftanh(d2); d3 = ftanh(d3); }
        *(float2*)&h0[y0] = make_float2(d0, d1);
        *(float2*)&h1[y0] = make_float2(d2, d3);
    }
}

// ---------------- fc1 (tanh) + fc2 fused (unchanged from R15) ----------------
__global__ __launch_bounds__(512, 2) void k_fc12_mma(const float* __restrict__ w1,
                                                     const float* __restrict__ b1,
                                                     const float* __restrict__ w2,
                                                     const float* __restrict__ b2,
                                                     float* __restrict__ out) {
    extern __shared__ unsigned smu[];
    float* sA = (float*)smu;                      // [128][AP] fp32
    unsigned* sB = (unsigned*)(sA + 128 * AP);    // [32][IBP]
    float* sred = (float*)(sB + 32 * IBP);        // [256]
    float* sb1  = sred + 256;                     // [128]
    float* sw2  = sb1 + 128;                      // [128]
    int x = blockIdx.x, b = blockIdx.y, tid = threadIdx.x;
    int wid = tid >> 5, lane = tid & 31, gid = lane >> 2, tig = lane & 3;
    int mt = wid & 7, nh = wid >> 3;
    int fbase = mt * 16, ybase = nh * 128;

    for (int idx = tid; idx < 128 * AP; idx += 512) {
        int f = idx / AP, c = idx % AP;
        sA[idx] = (c < 64) ? w1[c * FCN + f] : 0.f;
    }
    if (tid < 256) sred[tid] = 0.f;
    if (tid < 128) { sb1[tid] = b1[tid]; sw2[tid] = w2[tid]; }
    __syncthreads();

    float bias0 = sb1[fbase + gid], bias1 = sb1[fbase + gid + 8];
    float w20 = sw2[fbase + gid], w21 = sw2[fbase + gid + 8];
    float acc[16][4];
#pragma unroll
    for (int nt = 0; nt < 16; nt++) { acc[nt][0] = acc[nt][1] = bias0; acc[nt][2] = acc[nt][3] = bias1; }

    for (int hc = 0; hc < 2; hc++) {
        __syncthreads();
        for (int idx = tid; idx < 32 * 64; idx += 512) {
            int i = idx >> 6, q = idx & 63;
            float4 v = *(const float4*)&g_h[(((size_t)(b * 64 + hc * 32 + i)) * NN + x) * NN + q * 4];
            store_frag(sB, i, q, v);
        }
        __syncthreads();
#pragma unroll
        for (int ks = 0; ks < 4; ks++) {
            int k0 = ks * 8;
            int ca = hc * 32 + k0 + tig;
            unsigned ah0, al0, ah1, al1, ah2, al2, ah3, al3;
            split_tf(sA[(fbase + gid) * AP + ca], ah0, al0);
            split_tf(sA[(fbase + gid + 8) * AP + ca], ah1, al1);
            split_tf(sA[(fbase + gid) * AP + ca + 4], ah2, al2);
            split_tf(sA[(fbase + gid + 8) * AP + ca + 4], ah3, al3);
#pragma unroll
            for (int nt = 0; nt < 16; nt++) {
                int n = ybase + nt * 8 + gid;
                uint2 b0 = *(const uint2*)&sB[(k0 + tig) * IBP + 2 * n];
                uint2 b1 = *(const uint2*)&sB[(k0 + tig + 4) * IBP + 2 * n];
                MMA3(acc[nt], ah0,ah1,ah2,ah3, al0,al1,al2,al3, b0.x, b1.x, b0.y, b1.y);
            }
        }
    }

#pragma unroll
    for (int nt = 0; nt < 16; nt++) {
        float p0 = ftanh(acc[nt][0]) * w20 + ftanh(acc[nt][2]) * w21;
        float p1 = ftanh(acc[nt][1]) * w20 + ftanh(acc[nt][3]) * w21;
#pragma unroll
        for (int m = 4; m < 32; m <<= 1) {
            p0 += __shfl_xor_sync(0xffffffffu, p0, m);
            p1 += __shfl_xor_sync(0xffffffffu, p1, m);
        }
        if (lane < 4) {
            int y0 = ybase + nt * 8 + lane * 2;
            atomicAdd(&sred[y0], p0);
            atomicAdd(&sred[y0 + 1], p1);
        }
    }
    __syncthreads();
    if (tid < 256)
        out[((size_t)b * NN + x) * NN + tid] = sred[tid] + __ldg(&b2[0]);
}

// ---------------- launch ----------------
extern "C" void kernel_launch(void* const* d_in, const int* in_sizes, int n_in,
                              void* d_out, int out_size) {
    const float* x      = (const float*)d_in[0];
    const float* fc0_w  = (const float*)d_in[1];
    const float* fc0_b  = (const float*)d_in[2];
    const float* sp_w1  = (const float*)d_in[3];
    const float* sp_w2  = (const float*)d_in[4];
    const float* conv_w = (const float*)d_in[5];
    const float* conv_b = (const float*)d_in[6];
    const float* fc1_w  = (const float*)d_in[7];
    const float* fc1_b  = (const float*)d_in[8];
    const float* fc2_w  = (const float*)d_in[9];
    const float* fc2_b  = (const float*)d_in[10];
    float* out = (float*)d_out;

    const int SM_S1P    = 24 * SBP * 4;                                          // 50688
    const int SM_S2P    = (48 * F1P + 256 * PBP) * 4;                            // 107264
    const int SM_ILAYER = (64 * AP + 64 * 28) * 4 + (24 + 16) * IBP * 4;         // 107776
    const int SM_FC12   = 128 * AP * 4 + 32 * IBP * 4 + (256 + 128 + 128) * 4;   // 103424

    cudaFuncSetAttribute(k_s1p, cudaFuncAttributeMaxDynamicSharedMemorySize, SM_S1P);
    cudaFuncSetAttribute(k_s2p_mma, cudaFuncAttributeMaxDynamicSharedMemorySize, SM_S2P);
    cudaFuncSetAttribute(k_ilayer_mma, cudaFuncAttributeMaxDynamicSharedMemorySize, SM_ILAYER);
    cudaFuncSetAttribute(k_fc12_mma, cudaFuncAttributeMaxDynamicSharedMemorySize, SM_FC12);

    k_init<<<NN, 256>>>();
    k_wtrans<<<dim3(13, 128, LL * 2), dim3(32, 32)>>>(sp_w1, sp_w2);
    k_fc0<<<dim3(NN, BB), 256>>>(x, fc0_w, fc0_b);

    for (int l = 0; l < LL; l++) {
        k_s1p<<<(BB * CC * NN) / 128, 256, SM_S1P>>>();
        k_s2p_mma<<<BB * CC, 256, SM_S2P>>>();
        k_mix<<<MODES, 256>>>(l);
        k_istage1<<<BB * CC, 256>>>();
        k_ilayer_mma<<<dim3(NN, BB), 512, SM_ILAYER>>>(conv_w, conv_b, l, (l != LL - 1) ? 1 : 0);
    }

    k_fc12_mma<<<dim3(NN, BB), 512, SM_FC12>>>(fc1_w, fc1_b, fc2_w, fc2_b, out);
}

// round 17
// speedup vs baseline: 1.2885x; 1.1855x over previous
#include <cuda_runtime.h>
#include <math.h>

#define BB 8
#define CC 64
#define NN 256
#define M1 20
#define M2 20
#define RR 40
#define MODES 800
#define LL 3
#define FCN 128
#define AP 68           // A-matrix smem row pitch (floats)
#define SBP 528         // s1p B pitch (words)
#define IBP 520         // ilayer B pitch (words)
#define PBP 56          // s2p B pitch (words)
#define F1P 260         // s2p F1 pitch
#define OP 264          // fused fc OUT pitch (floats)

// ---------------- device scratch ----------------
__device__ float g_h[BB * CC * NN * NN];
__device__ float g_t1p[BB * CC * NN * M2];
__device__ float g_spec[MODES * BB * CC];
__device__ float g_spec2[BB * CC * MODES];
__device__ float g_t2[BB * CC * NN * M2];
__device__ float g_Wm[LL * MODES * CC * CC];
__device__ float g_F1[RR * NN];
__device__ float g_F2[M2 * NN];
__device__ float g_G1[NN * RR];
__device__ float g_G2[NN * M2];
__device__ float g_w1t[FCN * CC];     // fc1 weights transposed [f][c]

// ---------------- helpers ----------------
__device__ __forceinline__ void split_tf(float v, unsigned& hi, unsigned& lo) {
    unsigned h = __float_as_uint(v) & 0xffffe000u;
    hi = h;
    lo = __float_as_uint(v - __uint_as_float(h));
}
__device__ __forceinline__ void mma8(float& d0, float& d1, float& d2, float& d3,
                                     unsigned a0, unsigned a1, unsigned a2, unsigned a3,
                                     unsigned b0, unsigned b1) {
    asm("mma.sync.aligned.m16n8k8.row.col.f32.tf32.tf32.f32 "
        "{%0,%1,%2,%3},{%4,%5,%6,%7},{%8,%9},{%0,%1,%2,%3};"
        : "+f"(d0), "+f"(d1), "+f"(d2), "+f"(d3)
        : "r"(a0), "r"(a1), "r"(a2), "r"(a3), "r"(b0), "r"(b1));
}
#define MMA3(ACC, AH0,AH1,AH2,AH3, AL0,AL1,AL2,AL3, BH0,BH1, BL0,BL1)             \
    do {                                                                           \
        mma8(ACC[0],ACC[1],ACC[2],ACC[3], AH0,AH1,AH2,AH3, BL0,BL1);               \
        mma8(ACC[0],ACC[1],ACC[2],ACC[3], AL0,AL1,AL2,AL3, BH0,BH1);               \
        mma8(ACC[0],ACC[1],ACC[2],ACC[3], AH0,AH1,AH2,AH3, BH0,BH1);               \
    } while (0)
#define MMA3S(ACC, ACG, AH0,AH1,AH2,AH3, AL0,AL1,AL2,AL3, BH0,BH1, BL0,BL1)       \
    do {                                                                           \
        mma8(ACG[0],ACG[1],ACG[2],ACG[3], AH0,AH1,AH2,AH3, BL0,BL1);               \
        mma8(ACG[0],ACG[1],ACG[2],ACG[3], AL0,AL1,AL2,AL3, BH0,BH1);               \
        mma8(ACC[0],ACC[1],ACC[2],ACC[3], AH0,AH1,AH2,AH3, BH0,BH1);               \
    } while (0)

__device__ __forceinline__ float ftanh(float x) {
    float e = __expf(2.f * x);
    return 1.f - __fdividef(2.f, e + 1.f);
}
__device__ __forceinline__ void store_frag(unsigned* dst, int i, int q, float4 v) {
    unsigned h0, l0, h1, l1, h2, l2, h3, l3;
    split_tf(v.x, h0, l0); split_tf(v.y, h1, l1);
    split_tf(v.z, h2, l2); split_tf(v.w, h3, l3);
    *(uint4*)&dst[i * IBP + 8 * q]     = make_uint4(h0, l0, h1, l1);
    *(uint4*)&dst[i * IBP + 8 * q + 4] = make_uint4(h2, l2, h3, l3);
}

// ---------------- DCT basis tables ----------------
__global__ void k_init() {
    int x = blockIdx.x, t = threadIdx.x;
    if (t < RR) {
        int k = (t < M1) ? t : (216 + t);
        int m = (k * x) % 510;
        float cv = (float)cospi((double)m / 255.0);
        float cx = (x == 0 || x == 255) ? 1.f : 2.f;
        g_F1[t * NN + x] = cx * cv;
        float ck = (k == 0 || k == 255) ? 1.f : 2.f;
        g_G1[x * RR + t] = ck * cv;
    }
    if (t < M2) {
        int m = (t * x) % 510;
        float cv = (float)cospi((double)m / 255.0);
        float cy = (x == 0 || x == 255) ? 1.f : 2.f;
        g_F2[t * NN + x] = cy * cv;
        float cs = (t == 0) ? 1.f : 2.f;
        g_G2[x * M2 + t] = cs * cv;
    }
}

// ---------------- fc1 weight transpose (one block, once) ----------------
__global__ void k_wfc1(const float* __restrict__ w1) {
    int t = threadIdx.x;
    for (int idx = t; idx < FCN * CC; idx += 256) {
        int f = idx >> 6, c = idx & 63;
        g_w1t[idx] = w1[c * FCN + f];
    }
}

// ---------------- spectral weight transpose ----------------
__global__ void k_wtrans(const float* __restrict__ w1, const float* __restrict__ w2) {
    __shared__ float tile[32][33];
    int l = blockIdx.z >> 1, half = blockIdx.z & 1;
    const float* src = (half ? w2 : w1) + (size_t)l * CC * CC * (M1 * M2);
    float* dst = g_Wm + ((size_t)l * MODES + half * 400) * (CC * CC);
    int col = blockIdx.x * 32 + threadIdx.x;
    int row = blockIdx.y * 32 + threadIdx.y;
    if (col < 400) tile[threadIdx.y][threadIdx.x] = src[(size_t)row * 400 + col];
    __syncthreads();
    int drow = blockIdx.x * 32 + threadIdx.y;
    int dcol = blockIdx.y * 32 + threadIdx.x;
    if (drow < 400) dst[(size_t)drow * 4096 + dcol] = tile[threadIdx.x][threadIdx.y];
}

// ---------------- fc0 ----------------
__global__ void k_fc0(const float* __restrict__ x, const float* __restrict__ w,
                      const float* __restrict__ bias) {
    __shared__ float sw[3][CC];
    __shared__ float sb[CC];
    int xi = blockIdx.x, b = blockIdx.y, y = threadIdx.x;
    if (y < CC) { sw[0][y] = w[y]; sw[1][y] = w[CC + y]; sw[2][y] = w[2 * CC + y]; sb[y] = bias[y]; }
    __syncthreads();
    const float* xp = x + (((size_t)b * NN + xi) * NN + y) * 3;
    float d0 = xp[0], d1 = xp[1], d2 = xp[2];
    float* hp = g_h + ((size_t)(b * CC) * NN + xi) * NN + y;
#pragma unroll
    for (int c = 0; c < CC; c++)
        hp[(size_t)c * (NN * NN)] = sb[c] + d0 * sw[0][c] + d1 * sw[1][c] + d2 * sw[2][c];
}

// ---------------- forward DCT stage 1' ----------
__global__ __launch_bounds__(256) void k_s1p() {
    extern __shared__ unsigned smu[];
    unsigned* sB = smu;                // [24][SBP]
    int tid = threadIdx.x;
    int wid = tid >> 5, lane = tid & 31, gid = lane >> 2, tig = lane & 3;

    for (int idx = tid; idx < 24 * 256; idx += 256) {
        int n = idx >> 8, y = idx & 255;
        float v = (n < 20) ? g_F2[n * NN + y] : 0.f;
        split_tf(v, sB[n * SBP + 2 * y], sB[n * SBP + 2 * y + 1]);
    }
    __syncthreads();

    size_t row0 = (size_t)blockIdx.x * 128 + wid * 16;
    const float* A0 = g_h + (row0 + gid) * NN;
    const float* A1 = g_h + (row0 + gid + 8) * NN;

    float acc[3][4], acg[3][4];
#pragma unroll
    for (int i = 0; i < 3; i++) {
        acc[i][0] = acc[i][1] = acc[i][2] = acc[i][3] = 0.f;
        acg[i][0] = acg[i][1] = acg[i][2] = acg[i][3] = 0.f;
    }

#pragma unroll 4
    for (int k0 = 0; k0 < 256; k0 += 8) {
        float2 p0 = *(const float2*)&A0[k0 + 2 * tig];
        float2 p1 = *(const float2*)&A1[k0 + 2 * tig];
        unsigned ah0, al0, ah1, al1, ah2, al2, ah3, al3;
        split_tf(p0.x, ah0, al0); split_tf(p1.x, ah1, al1);
        split_tf(p0.y, ah2, al2); split_tf(p1.y, ah3, al3);
#pragma unroll
        for (int nt = 0; nt < 3; nt++) {
            int n = nt * 8 + gid;
            uint4 bv = *(const uint4*)&sB[n * SBP + 2 * k0 + 4 * tig];
            MMA3S(acc[nt], acg[nt], ah0,ah1,ah2,ah3, al0,al1,al2,al3, bv.x, bv.z, bv.y, bv.w);
        }
    }

    float* t0 = g_t1p + (row0 + gid) * M2;
    float* t1 = g_t1p + (row0 + gid + 8) * M2;
#pragma unroll
    for (int nt = 0; nt < 3; nt++) {
        int c0 = nt * 8 + tig * 2;
        if (c0 < 20) {
            *(float2*)&t0[c0] = make_float2(acc[nt][0] + acg[nt][0], acc[nt][1] + acg[nt][1]);
            *(float2*)&t1[c0] = make_float2(acc[nt][2] + acg[nt][2], acc[nt][3] + acg[nt][3]);
        }
    }
}

// ---------------- forward DCT stage 2' (MMA) ---------
__global__ __launch_bounds__(256) void k_s2p_mma() {
    extern __shared__ unsigned smu[];
    float* sA = (float*)smu;                 // [48][F1P]
    unsigned* sB = smu + 48 * F1P;           // [256][PBP]
    int bc = blockIdx.x, tid = threadIdx.x;
    int wid = tid >> 5, lane = tid & 31, gid = lane >> 2, tig = lane & 3;

    for (int idx = tid; idx < 48 * 256; idx += 256) {
        int r = idx >> 8, xx = idx & 255;
        sA[r * F1P + xx] = (r < RR) ? g_F1[r * NN + xx] : 0.f;
    }
    const float* tb = g_t1p + (size_t)bc * (NN * M2);
    for (int idx = tid; idx < 256 * 24; idx += 256) {
        int xx = idx / 24, s = idx % 24;
        float v = (s < 20) ? tb[xx * 20 + s] : 0.f;
        split_tf(v, sB[xx * PBP + 2 * s], sB[xx * PBP + 2 * s + 1]);
    }
    __syncthreads();

    float acc[3][4];
#pragma unroll
    for (int i = 0; i < 3; i++) { acc[i][0] = acc[i][1] = acc[i][2] = acc[i][3] = 0.f; }

    int mt = wid % 3, kh = wid / 3;
    if (wid < 6) {
        int mtb = mt * 16;
#pragma unroll 4
        for (int ks = 0; ks < 16; ks++) {
            int k0 = kh * 128 + ks * 8;
            unsigned ah0, al0, ah1, al1, ah2, al2, ah3, al3;
            split_tf(sA[(mtb + gid) * F1P + k0 + tig], ah0, al0);
            split_tf(sA[(mtb + gid + 8) * F1P + k0 + tig], ah1, al1);
            split_tf(sA[(mtb + gid) * F1P + k0 + tig + 4], ah2, al2);
            split_tf(sA[(mtb + gid + 8) * F1P + k0 + tig + 4], ah3, al3);
#pragma unroll
            for (int nt = 0; nt < 3; nt++) {
                int n = nt * 8 + gid;
                uint2 b0 = *(const uint2*)&sB[(k0 + tig) * PBP + 2 * n];
                uint2 b1 = *(const uint2*)&sB[(k0 + tig + 4) * PBP + 2 * n];
                MMA3(acc[nt], ah0,ah1,ah2,ah3, al0,al1,al2,al3, b0.x, b1.x, b0.y, b1.y);
            }
        }
    }
    __syncthreads();
    float* red = (float*)smu;
    if (wid < 6) {
        int mtb = mt * 16;
#pragma unroll
        for (int nt = 0; nt < 3; nt++) {
            int c0 = nt * 8 + tig * 2;
            int r0 = mtb + gid, r1 = r0 + 8;
            red[kh * 1152 + r0 * 24 + c0]     = acc[nt][0];
            red[kh * 1152 + r0 * 24 + c0 + 1] = acc[nt][1];
            red[kh * 1152 + r1 * 24 + c0]     = acc[nt][2];
            red[kh * 1152 + r1 * 24 + c0 + 1] = acc[nt][3];
        }
    }
    __syncthreads();
    for (int idx = tid; idx < 48 * 24; idx += 256) {
        int r = idx / 24, s = idx % 24;
        if (r < RR && s < 20)
            g_spec[(size_t)(r * M2 + s) * (BB * CC) + bc] = red[idx] + red[1152 + idx];
    }
}

// ---------------- per-mode channel mix ----------------
__global__ __launch_bounds__(256) void k_mix(int l) {
    __shared__ float sW[CC * CC];
    __shared__ float sS[BB * CC];
    int m = blockIdx.x, t = threadIdx.x;
    const float4* Wp = (const float4*)(g_Wm + ((size_t)l * MODES + m) * (CC * CC));
#pragma unroll
    for (int j = 0; j < 4; j++) ((float4*)sW)[t + j * 256] = Wp[t + j * 256];
    if (t < 128) ((float4*)sS)[t] = ((const float4*)(g_spec + (size_t)m * (BB * CC)))[t];
    __syncthreads();
#pragma unroll
    for (int k = 0; k < 2; k++) {
        int idx = t + k * 256;
        int b = idx >> 6, o = idx & 63;
        float a0 = 0.f, a1 = 0.f;
#pragma unroll
        for (int i = 0; i < 32; i++) a0 += sS[b * CC + i] * sW[i * CC + o];
#pragma unroll
        for (int i = 32; i < 64; i++) a1 += sS[b * CC + i] * sW[i * CC + o];
        g_spec2[(size_t)(b * CC + o) * MODES + m] = a0 + a1;
    }
}

// ---------------- inverse stage 1 ----------------
__global__ __launch_bounds__(256) void k_istage1() {
    __shared__ float sS[MODES];
    int bo = blockIdx.x, x = threadIdx.x;
    for (int i = x; i < MODES; i += 256) sS[i] = g_spec2[(size_t)bo * MODES + i];
    __syncthreads();
    float g1r[RR];
    const float4* gp = (const float4*)(g_G1 + x * RR);
#pragma unroll
    for (int j = 0; j < RR / 4; j++) {
        float4 v = gp[j];
        g1r[4 * j] = v.x; g1r[4 * j + 1] = v.y; g1r[4 * j + 2] = v.z; g1r[4 * j + 3] = v.w;
    }
    float acc[M2];
#pragma unroll
    for (int s = 0; s < M2; s++) acc[s] = 0.f;
#pragma unroll 4
    for (int r = 0; r < RR; r++) {
        float g = g1r[r];
#pragma unroll
        for (int s = 0; s < M2; s++) acc[s] += g * sS[r * M2 + s];
    }
    float* tp = g_t2 + ((size_t)bo * NN + x) * M2;
#pragma unroll
    for (int s = 0; s < M2; s++) tp[s] = acc[s];
}

// ---------------- fused layer update + (last layer) fc1/fc2 ---------
__global__ __launch_bounds__(512, 2) void k_ilayer_mma(const float* __restrict__ conv_w,
                                                       const float* __restrict__ conv_b,
                                                       const float* __restrict__ b1,
                                                       const float* __restrict__ w2,
                                                       const float* __restrict__ b2,
                                                       float* __restrict__ out,
                                                       int l, int do_tanh, int do_fc) {
    extern __shared__ unsigned smu[];
    float* sA1 = (float*)smu;                    // [64][AP]
    float* sA2 = sA1 + 64 * AP;                  // [64][28]
    unsigned* sB  = (unsigned*)(sA2 + 64 * 28);  // [24][IBP]
    unsigned* sB2 = sB + 24 * IBP;               // [16][IBP]
    int x = blockIdx.x, b = blockIdx.y, tid = threadIdx.x;
    int wid = tid >> 5, lane = tid & 31, gid = lane >> 2, tig = lane & 3;
    int mt = wid & 3, nh = wid >> 2;
    int obase = mt * 16, ybase = nh * 64;

    const float* cw = conv_w + (size_t)l * CC * CC;
    for (int idx = tid; idx < 64 * AP; idx += 512) {
        int o = idx / AP, i = idx % AP;
        sA1[idx] = (i < 64) ? cw[o * 64 + i] : 0.f;
    }
    for (int idx = tid; idx < 64 * 28; idx += 512) {
        int o = idx / 28, s = idx % 28;
        sA2[idx] = (s < 20) ? g_t2[(((size_t)(b * 64 + o)) * NN + x) * M2 + s] : 0.f;
    }
    for (int idx = tid; idx < 24 * 256; idx += 512) {
        int s = idx >> 8, y = idx & 255;
        float v = (s < 20) ? g_G2[y * M2 + s] : 0.f;
        split_tf(v, sB[s * IBP + 2 * y], sB[s * IBP + 2 * y + 1]);
    }
    __syncthreads();

    float bias0 = __ldg(&conv_b[l * 64 + obase + gid]);
    float bias1 = __ldg(&conv_b[l * 64 + obase + gid + 8]);
    float acc[8][4];
#pragma unroll
    for (int nt = 0; nt < 8; nt++) { acc[nt][0] = acc[nt][1] = bias0; acc[nt][2] = acc[nt][3] = bias1; }

    const float* hbase = &g_h[((size_t)(b * 64) * NN + x) * NN];
    int si0 = tid >> 6, sq0 = tid & 63;
    int si1 = (tid + 512) >> 6, sq1 = (tid + 512) & 63;

    float4 v0 = *(const float4*)&hbase[(size_t)si0 * (NN * NN) + sq0 * 4];
    float4 v1 = *(const float4*)&hbase[(size_t)si1 * (NN * NN) + sq1 * 4];

    // ---- DCT term ----
#pragma unroll
    for (int ks = 0; ks < 3; ks++) {
        int k0 = ks * 8;
        unsigned ah0, al0, ah1, al1, ah2, al2, ah3, al3;
        split_tf(sA2[(obase + gid) * 28 + k0 + tig], ah0, al0);
        split_tf(sA2[(obase + gid + 8) * 28 + k0 + tig], ah1, al1);
        split_tf(sA2[(obase + gid) * 28 + k0 + tig + 4], ah2, al2);
        split_tf(sA2[(obase + gid + 8) * 28 + k0 + tig + 4], ah3, al3);
#pragma unroll
        for (int nt = 0; nt < 8; nt++) {
            int n = ybase + nt * 8 + gid;
            uint2 b0 = *(const uint2*)&sB[(k0 + tig) * IBP + 2 * n];
            uint2 b1 = *(const uint2*)&sB[(k0 + tig + 4) * IBP + 2 * n];
            MMA3(acc[nt], ah0,ah1,ah2,ah3, al0,al1,al2,al3, b0.x, b1.x, b0.y, b1.y);
        }
    }
    __syncthreads();
    store_frag(sB2, si0, sq0, v0);
    store_frag(sB2, si1, sq1, v1);
    __syncthreads();

    // ---- conv term: 4 chunks double-buffered ----
    for (int hc = 0; hc < 4; hc++) {
        if (hc < 3) {
            const float* hb = hbase + (size_t)((hc + 1) * 16) * (NN * NN);
            v0 = *(const float4*)&hb[(size_t)si0 * (NN * NN) + sq0 * 4];
            v1 = *(const float4*)&hb[(size_t)si1 * (NN * NN) + sq1 * 4];
        }
        const unsigned* bufc = (hc & 1) ? sB : sB2;
#pragma unroll
        for (int ks = 0; ks < 2; ks++) {
            int k0 = ks * 8;
            int ca = hc * 16 + k0 + tig;
            unsigned ah0, al0, ah1, al1, ah2, al2, ah3, al3;
            split_tf(sA1[(obase + gid) * AP + ca], ah0, al0);
            split_tf(sA1[(obase + gid + 8) * AP + ca], ah1, al1);
            split_tf(sA1[(obase + gid) * AP + ca + 4], ah2, al2);
            split_tf(sA1[(obase + gid + 8) * AP + ca + 4], ah3, al3);
#pragma unroll
            for (int nt = 0; nt < 8; nt++) {
                int n = ybase + nt * 8 + gid;
                uint2 b0 = *(const uint2*)&bufc[(k0 + tig) * IBP + 2 * n];
                uint2 b1 = *(const uint2*)&bufc[(k0 + tig + 4) * IBP + 2 * n];
                MMA3(acc[nt], ah0,ah1,ah2,ah3, al0,al1,al2,al3, b0.x, b1.x, b0.y, b1.y);
            }
        }
        if (hc < 3) {
            unsigned* dst = ((hc + 1) & 1) ? sB : sB2;
            store_frag(dst, si0, sq0, v0);
            store_frag(dst, si1, sq1, v1);
        }
        __syncthreads();
    }

    int r0 = obase + gid, r1 = r0 + 8;
    if (!do_fc) {
        float* h0 = &g_h[(((size_t)(b * 64 + r0)) * NN + x) * NN];
        float* h1 = &g_h[(((size_t)(b * 64 + r1)) * NN + x) * NN];
#pragma unroll
        for (int nt = 0; nt < 8; nt++) {
            int y0 = ybase + nt * 8 + tig * 2;
            float d0 = acc[nt][0], d1 = acc[nt][1], d2 = acc[nt][2], d3 = acc[nt][3];
            if (do_tanh) { d0 = ftanh(d0); d1 = ftanh(d1); d2 = ftanh(d2); d3 = ftanh(d3); }
            *(float2*)&h0[y0] = make_float2(d0, d1);
            *(float2*)&h1[y0] = make_float2(d2, d3);
        }
    } else {
        // ---- fused fc1/fc2: OUT -> smem, HID = W1T*OUT, out = sum tanh(HID)*w2 + b2 ----
        float* sO   = (float*)smu;            // [64][OP]
        float* sW1  = sO + 64 * OP;           // [128][AP]
        float* sred = sW1 + 128 * AP;         // [256]
        float* sb1v = sred + 256;             // [128]
        float* sw2v = sb1v + 128;             // [128]
#pragma unroll
        for (int nt = 0; nt < 8; nt++) {
            int y0 = ybase + nt * 8 + tig * 2;
            *(float2*)&sO[r0 * OP + y0] = make_float2(acc[nt][0], acc[nt][1]);
            *(float2*)&sO[r1 * OP + y0] = make_float2(acc[nt][2], acc[nt][3]);
        }
        for (int idx = tid; idx < 128 * AP; idx += 512) {
            int f = idx / AP, c = idx % AP;
            sW1[idx] = (c < 64) ? g_w1t[f * 64 + c] : 0.f;
        }
        if (tid < 256) sred[tid] = 0.f;
        if (tid < 128) { sb1v[tid] = b1[tid]; sw2v[tid] = w2[tid]; }
        __syncthreads();

        int mt2 = wid & 3, nh2 = wid >> 2;
        int yb2 = nh2 * 64;
        for (int p = 0; p < 2; p++) {
            int fbase = p * 64 + mt2 * 16;
            float bb0 = sb1v[fbase + gid], bb1 = sb1v[fbase + gid + 8];
            float w20 = sw2v[fbase + gid], w21 = sw2v[fbase + gid + 8];
            float ac2[8][4];
#pragma unroll
            for (int nt = 0; nt < 8; nt++) { ac2[nt][0] = ac2[nt][1] = bb0; ac2[nt][2] = ac2[nt][3] = bb1; }
#pragma unroll
            for (int ks = 0; ks < 8; ks++) {
                int k0 = ks * 8;
                unsigned ah0, al0, ah1, al1, ah2, al2, ah3, al3;
                split_tf(sW1[(fbase + gid) * AP + k0 + tig], ah0, al0);
                split_tf(sW1[(fbase + gid + 8) * AP + k0 + tig], ah1, al1);
                split_tf(sW1[(fbase + gid) * AP + k0 + tig + 4], ah2, al2);
                split_tf(sW1[(fbase + gid + 8) * AP + k0 + tig + 4], ah3, al3);
#pragma unroll
                for (int nt = 0; nt < 8; nt++) {
                    int n = yb2 + nt * 8 + gid;
                    unsigned bh0, bl0, bh1, bl1;
                    split_tf(sO[(k0 + tig) * OP + n], bh0, bl0);
                    split_tf(sO[(k0 + tig + 4) * OP + n], bh1, bl1);
                    MMA3(ac2[nt], ah0,ah1,ah2,ah3, al0,al1,al2,al3, bh0,bh1, bl0,bl1);
                }
            }
#pragma unroll
            for (int nt = 0; nt < 8; nt++) {
                float p0 = ftanh(ac2[nt][0]) * w20 + ftanh(ac2[nt][2]) * w21;
                float p1 = ftanh(ac2[nt][1]) * w20 + ftanh(ac2[nt][3]) * w21;
#pragma unroll
                for (int m = 4; m < 32; m <<= 1) {
                    p0 += __shfl_xor_sync(0xffffffffu, p0, m);
                    p1 += __shfl_xor_sync(0xffffffffu, p1, m);
                }
                if (lane < 4) {
                    int y0 = yb2 + nt * 8 + lane * 2;
                    atomicAdd(&sred[y0], p0);
                    atomicAdd(&sred[y0 + 1], p1);
                }
            }
        }
        __syncthreads();
        if (tid < 256)
            out[((size_t)b * NN + x) * NN + tid] = sred[tid] + __ldg(&b2[0]);
    }
}

// ---------------- launch ----------------
extern "C" void kernel_launch(void* const* d_in, const int* in_sizes, int n_in,
                              void* d_out, int out_size) {
    const float* x      = (const float*)d_in[0];
    const float* fc0_w  = (const float*)d_in[1];
    const float* fc0_b  = (const float*)d_in[2];
    const float* sp_w1  = (const float*)d_in[3];
    const float* sp_w2  = (const float*)d_in[4];
    const float* conv_w = (const float*)d_in[5];
    const float* conv_b = (const float*)d_in[6];
    const float* fc1_w  = (const float*)d_in[7];
    const float* fc1_b  = (const float*)d_in[8];
    const float* fc2_w  = (const float*)d_in[9];
    const float* fc2_b  = (const float*)d_in[10];
    float* out = (float*)d_out;

    const int SM_S1P    = 24 * SBP * 4;                                          // 50688
    const int SM_S2P    = (48 * F1P + 256 * PBP) * 4;                            // 107264
    const int SM_ILAYER = (64 * AP + 64 * 28) * 4 + (24 + 16) * IBP * 4;         // 107776
    // fc phase needs (64*OP + 128*AP + 512) * 4 = 104448 <= SM_ILAYER (aliased)

    cudaFuncSetAttribute(k_s1p, cudaFuncAttributeMaxDynamicSharedMemorySize, SM_S1P);
    cudaFuncSetAttribute(k_s2p_mma, cudaFuncAttributeMaxDynamicSharedMemorySize, SM_S2P);
    cudaFuncSetAttribute(k_ilayer_mma, cudaFuncAttributeMaxDynamicSharedMemorySize, SM_ILAYER);

    k_init<<<NN, 256>>>();
    k_wfc1<<<1, 256>>>(fc1_w);
    k_wtrans<<<dim3(13, 128, LL * 2), dim3(32, 32)>>>(sp_w1, sp_w2);
    k_fc0<<<dim3(NN, BB), 256>>>(x, fc0_w, fc0_b);

    for (int l = 0; l < LL; l++) {
        k_s1p<<<(BB * CC * NN) / 128, 256, SM_S1P>>>();
        k_s2p_mma<<<BB * CC, 256, SM_S2P>>>();
        k_mix<<<MODES, 256>>>(l);
        k_istage1<<<BB * CC, 256>>>();
        k_ilayer_mma<<<dim3(NN, BB), 512, SM_ILAYER>>>(conv_w, conv_b, fc1_b, fc2_w, fc2_b,
                                                       out, l, (l != LL - 1) ? 1 : 0,
                                                       (l == LL - 1) ? 1 : 0);
    }
}